// round 13
// baseline (speedup 1.0000x reference)
#include <cuda_runtime.h>
#include <cuda_bf16.h>
#include <stdint.h>
#include <math.h>

#define B_   8192
#define C_   4
#define D_   256
#define E_   8
#define H_   256
#define O_   128
#define CO_  512
#define HQ_  512
#define AQ_  18
#define N_   (B_ * C_)
#define NT_  256
#define MT_  512

__device__ float g_result[B_ * CO_];
__device__ float g_out   [B_ * CO_];
__device__ float g_x2    [N_ * D_];
__device__ float g_hq    [B_ * HQ_];
__device__ float g_s     [B_];
__device__ __nv_bfloat16 g_xs  [2 * N_ * D_];
__device__ __nv_bfloat16 g_w1t [2 * E_ * H_ * D_];
__device__ __nv_bfloat16 g_w2t [2 * E_ * O_ * H_];
__device__ __nv_bfloat16 g_wrt [2 * D_ * O_];
__device__ __nv_bfloat16 g_wq1t[2 * HQ_ * CO_];

__device__ __forceinline__ uint32_t smem_u32(const void* p) {
    uint32_t a;
    asm("{ .reg .u64 t; cvta.to.shared.u64 t, %1; cvt.u32.u64 %0, t; }" : "=r"(a) : "l"(p));
    return a;
}
__device__ __forceinline__ void ldsm4(uint32_t* r, uint32_t a) {
    asm volatile("ldmatrix.sync.aligned.m8n8.x4.shared.b16 {%0,%1,%2,%3}, [%4];"
                 : "=r"(r[0]), "=r"(r[1]), "=r"(r[2]), "=r"(r[3]) : "r"(a));
}
__device__ __forceinline__ void mma16816(float* c, const uint32_t* a, const uint32_t* b) {
    asm volatile("mma.sync.aligned.m16n8k16.row.col.f32.bf16.bf16.f32 "
                 "{%0,%1,%2,%3}, {%4,%5,%6,%7}, {%8,%9}, {%0,%1,%2,%3};"
                 : "+f"(c[0]), "+f"(c[1]), "+f"(c[2]), "+f"(c[3])
                 : "r"(a[0]), "r"(a[1]), "r"(a[2]), "r"(a[3]), "r"(b[0]), "r"(b[1]));
}
#define CPA(d, s)   asm volatile("cp.async.ca.shared.global [%0], [%1], 16;" :: "r"(d), "l"(s))
#define CPCOMMIT()  asm volatile("cp.async.commit_group;")
#define CPWAIT1()   asm volatile("cp.async.wait_group 1;" ::: "memory")
#define CPWAIT0()   asm volatile("cp.async.wait_group 0;" ::: "memory")

__device__ __forceinline__ void split2(float x, unsigned short& h, unsigned short& l) {
    __nv_bfloat16 b0 = __float2bfloat16(x);
    float r = x - __bfloat162float(b0);
    __nv_bfloat16 b1 = __float2bfloat16(r);
    h = __bfloat16_as_ushort(b0); l = __bfloat16_as_ushort(b1);
}
__device__ __forceinline__ uint32_t pack2(unsigned short a, unsigned short b) {
    return (uint32_t)a | ((uint32_t)b << 16);
}

// ---------------- split kernels (2-plane) ----------------
__global__ void split_x_kernel(const float* __restrict__ src, __nv_bfloat16* __restrict__ dst) {
    size_t i4 = (size_t)blockIdx.x * 256 + threadIdx.x;
    float4 v = ((const float4*)src)[i4];
    float xv[4] = {v.x, v.y, v.z, v.w};
    unsigned short hb[4], lb[4];
    #pragma unroll
    for (int j = 0; j < 4; j++) split2(xv[j], hb[j], lb[j]);
    const size_t S = (size_t)N_ * D_ / 4;
    uint2 u;
    u.x = pack2(hb[0], hb[1]); u.y = pack2(hb[2], hb[3]); ((uint2*)dst)[i4] = u;
    u.x = pack2(lb[0], lb[1]); u.y = pack2(lb[2], lb[3]); ((uint2*)dst)[i4 + S] = u;
}
__global__ void split_w1_kernel(const float* __restrict__ We1) {
    int idx = blockIdx.x * 256 + threadIdx.x;
    int e = idx >> 16, h = (idx >> 8) & 255, d = idx & 255;
    unsigned short hb, lb;
    split2(We1[((e * D_) + d) * H_ + h], hb, lb);
    g_w1t[idx] = __ushort_as_bfloat16(hb);
    g_w1t[idx + E_ * H_ * D_] = __ushort_as_bfloat16(lb);
}
__global__ void split_w2_kernel(const float* __restrict__ We2) {
    int idx = blockIdx.x * 256 + threadIdx.x;
    int e = idx >> 15, o = (idx >> 8) & 127, h = idx & 255;
    unsigned short hb, lb;
    split2(We2[((e * H_) + h) * O_ + o], hb, lb);
    g_w2t[idx] = __ushort_as_bfloat16(hb);
    g_w2t[idx + E_ * O_ * H_] = __ushort_as_bfloat16(lb);
}
__global__ void split_wr_kernel(const float* __restrict__ Wr) {
    int idx = blockIdx.x * 256 + threadIdx.x;
    int m = idx >> 7, k = idx & 127;
    unsigned short hb, lb;
    split2(Wr[k * D_ + m], hb, lb);
    g_wrt[idx] = __ushort_as_bfloat16(hb);
    g_wrt[idx + D_ * O_] = __ushort_as_bfloat16(lb);
}
__global__ void split_wq1_kernel(const float* __restrict__ Wq1) {
    int idx = blockIdx.x * 256 + threadIdx.x;
    int m = idx >> 9, k = idx & 511;
    unsigned short hb, lb;
    split2(Wq1[k * HQ_ + m], hb, lb);
    g_wq1t[idx] = __ushort_as_bfloat16(hb);
    g_wq1t[idx + HQ_ * CO_] = __ushort_as_bfloat16(lb);
}

// ---------------- MoE mma.sync kernel (16 warps, m32n16 tiles) ----------------
#define XPL   33792
#define HPL   17408
#define WPL   18432
#define WBUF  36864
#define XS_OFF 0
#define HB_OFF 67584
#define WB_OFF 102400
#define LG_OFF 212992
#define MOE_SMEM 215040
#define NCHUNK 96

__global__ void __launch_bounds__(MT_, 1)
moe_mma_kernel(const float* __restrict__ Xf, const __nv_bfloat16* __restrict__ XS,
               const __nv_bfloat16* __restrict__ W1T, const __nv_bfloat16* __restrict__ W2T,
               const float* __restrict__ be1, const float* __restrict__ be2,
               const float* __restrict__ Wg,  const float* __restrict__ bg,
               float* __restrict__ Out, const float* __restrict__ S)
{
    extern __shared__ char sm[];
    const int tid = threadIdx.x, lane = tid & 31, wid = tid >> 5;
    const int n0 = blockIdx.x * 64;

    if (S) {
        const int b0 = n0 >> 2;
        bool act = false;
        #pragma unroll
        for (int i = 0; i < 16; i++) act |= (S[b0 + i] != 0.0f);
        if (!act) return;
    }

    const uint32_t sb = smem_u32(sm);
    float* LG = (float*)(sm + LG_OFF);
    const size_t XST = (size_t)N_ * D_;
    const size_t W1S = (size_t)E_ * H_ * D_, W2S = (size_t)E_ * O_ * H_;

    // prologue: chunks 0,1 (W1 e=0) — overlap X-load + gating
    #pragma unroll
    for (int q = 0; q < 2; q++) {
        #pragma unroll
        for (int it = 0; it < 4; it++) {
            int idx = tid + it * 512;
            int p = idx >> 10, rem = idx & 1023, nn = rem >> 3, c8 = rem & 7;
            CPA(sb + WB_OFF + q * WBUF + p * WPL + nn * 144 + c8 * 16,
                W1T + (size_t)p * W1S + (size_t)nn * D_ + q * 64 + c8 * 8);
        }
        CPCOMMIT();
    }

    // X planes into padded smem
    #pragma unroll
    for (int it = 0; it < 8; it++) {
        int idx = tid + it * 512;
        int p = idx >> 11, rem = idx & 2047;
        int row = rem >> 5, c8 = rem & 31;
        uint4 v = *(const uint4*)(XS + (size_t)p * XST + (size_t)(n0 + row) * D_ + c8 * 8);
        *(uint4*)(sm + XS_OFF + p * XPL + row * 528 + c8 * 16) = v;
    }
    // gating logits (fp32): one logit per thread (64 tokens x 8 experts = 512)
    {
        int t = tid >> 3, e0 = tid & 7;
        float a0 = 0.f;
        const float* xr = Xf + (size_t)(n0 + t) * D_;
        for (int k = 0; k < D_; k += 4) {
            float4 xv = *(const float4*)(xr + k);
            a0 += xv.x * Wg[(k + 0) * 8 + e0] + xv.y * Wg[(k + 1) * 8 + e0]
                + xv.z * Wg[(k + 2) * 8 + e0] + xv.w * Wg[(k + 3) * 8 + e0];
        }
        LG[t * 8 + e0] = a0 + bg[e0];
    }
    __syncthreads();
    if (tid < 64) {
        float m = -1e30f;
        #pragma unroll
        for (int e = 0; e < 8; e++) m = fmaxf(m, LG[tid * 8 + e]);
        float ex[8], ss = 0.f;
        #pragma unroll
        for (int e = 0; e < 8; e++) { ex[e] = expf(LG[tid * 8 + e] - m); ss += ex[e]; }
        float inv = 1.0f / ss;
        #pragma unroll
        for (int e = 0; e < 8; e++) LG[tid * 8 + e] = ex[e] * inv;
    }

    const int mw = (wid >> 3) * 32, nw = (wid & 7) * 16;
    const int PA[3] = {0, 0, 1};
    const int PB[3] = {0, 1, 0};

    float D2[2][2][4];
    #pragma unroll
    for (int i = 0; i < 2; i++)
        #pragma unroll
        for (int j = 0; j < 2; j++)
            #pragma unroll
            for (int q = 0; q < 4; q++) D2[i][j][q] = 0.f;

    const uint32_t aoffX  = XS_OFF + (mw + (lane & 15)) * 528 + ((lane >> 4) << 3) * 2;
    const uint32_t aoffH  = HB_OFF + (mw + (lane & 15)) * 272 + ((lane >> 4) << 3) * 2;
    const uint32_t boffW4 = WB_OFF + (nw + (lane >> 4) * 8 + (lane & 7)) * 144 + ((lane >> 3) & 1) * 16;

    int gchunk = 0;
    for (int e8 = 0; e8 < 16; e8++) {
        const int e = e8 >> 1, half = e8 & 1;
        float C1[2][2][4];
        #pragma unroll
        for (int i = 0; i < 2; i++)
            #pragma unroll
            for (int j = 0; j < 2; j++)
                #pragma unroll
                for (int q = 0; q < 4; q++) C1[i][j][q] = 0.f;

        for (int c = 0; c < 6; c++, gchunk++) {
            if (gchunk == NCHUNK - 1) { CPWAIT0(); } else { CPWAIT1(); }
            __syncthreads();

            const uint32_t wb = sb + boffW4 + (gchunk % 3) * WBUF;
            if (c < 4) {
                #pragma unroll
                for (int ks = 0; ks < 4; ks++) {
                    const int kg = c * 64 + ks * 16;
                    uint32_t A[2][2][4], Bf[2][2][2];
                    #pragma unroll
                    for (int i = 0; i < 2; i++)
                        #pragma unroll
                        for (int p = 0; p < 2; p++)
                            ldsm4(A[i][p], sb + aoffX + p * XPL + i * 16 * 528 + kg * 2);
                    #pragma unroll
                    for (int p = 0; p < 2; p++) {
                        uint32_t r[4];
                        ldsm4(r, wb + p * WPL + ks * 32);
                        Bf[0][p][0] = r[0]; Bf[0][p][1] = r[1];
                        Bf[1][p][0] = r[2]; Bf[1][p][1] = r[3];
                    }
                    #pragma unroll
                    for (int pr = 0; pr < 3; pr++)
                        #pragma unroll
                        for (int i = 0; i < 2; i++)
                            #pragma unroll
                            for (int j = 0; j < 2; j++)
                                mma16816(C1[i][j], A[i][PA[pr]], Bf[j][PB[pr]]);
                }
                if (c == 3) {
                    // epilogue: hbuf = split2(g * relu(C1 + be1))
                    #pragma unroll
                    for (int i = 0; i < 2; i++) {
                        int r0 = mw + i * 16 + (lane >> 2);
                        float ga = LG[r0 * 8 + e], gb = LG[(r0 + 8) * 8 + e];
                        #pragma unroll
                        for (int j = 0; j < 2; j++) {
                            int col = nw + j * 8 + (lane & 3) * 2;
                            float b1a = be1[e * H_ + half * 128 + col];
                            float b1b = be1[e * H_ + half * 128 + col + 1];
                            float v0 = fmaxf(C1[i][j][0] + b1a, 0.f) * ga;
                            float v1 = fmaxf(C1[i][j][1] + b1b, 0.f) * ga;
                            float v2 = fmaxf(C1[i][j][2] + b1a, 0.f) * gb;
                            float v3 = fmaxf(C1[i][j][3] + b1b, 0.f) * gb;
                            unsigned short h0, l0, h1, l1;
                            uint32_t base0 = HB_OFF + r0 * 272 + col * 2;
                            uint32_t base1 = HB_OFF + (r0 + 8) * 272 + col * 2;
                            split2(v0, h0, l0); split2(v1, h1, l1);
                            *(uint32_t*)(sm + base0)       = pack2(h0, h1);
                            *(uint32_t*)(sm + base0 + HPL) = pack2(l0, l1);
                            split2(v2, h0, l0); split2(v3, h1, l1);
                            *(uint32_t*)(sm + base1)       = pack2(h0, h1);
                            *(uint32_t*)(sm + base1 + HPL) = pack2(l0, l1);
                        }
                    }
                }
            } else {
                #pragma unroll
                for (int ks = 0; ks < 4; ks++) {
                    const int kl = (c - 4) * 64 + ks * 16;
                    uint32_t A[2][2][4], Bf[2][2][2];
                    #pragma unroll
                    for (int i = 0; i < 2; i++)
                        #pragma unroll
                        for (int p = 0; p < 2; p++)
                            ldsm4(A[i][p], sb + aoffH + p * HPL + i * 16 * 272 + kl * 2);
                    #pragma unroll
                    for (int p = 0; p < 2; p++) {
                        uint32_t r[4];
                        ldsm4(r, wb + p * WPL + ks * 32);
                        Bf[0][p][0] = r[0]; Bf[0][p][1] = r[1];
                        Bf[1][p][0] = r[2]; Bf[1][p][1] = r[3];
                    }
                    #pragma unroll
                    for (int pr = 0; pr < 3; pr++)
                        #pragma unroll
                        for (int i = 0; i < 2; i++)
                            #pragma unroll
                            for (int j = 0; j < 2; j++)
                                mma16816(D2[i][j], A[i][PA[pr]], Bf[j][PB[pr]]);
                }
            }

            const int q = gchunk + 2;
            if (q < NCHUNK) {
                const int qe8 = q / 6, qc = q - qe8 * 6;
                const int qe = qe8 >> 1, qh = qe8 & 1;
                const uint32_t dbase = sb + WB_OFF + (q % 3) * WBUF;
                #pragma unroll
                for (int it = 0; it < 4; it++) {
                    int idx = tid + it * 512;
                    int p = idx >> 10, rem = idx & 1023, nn = rem >> 3, c8 = rem & 7;
                    const __nv_bfloat16* src;
                    if (qc < 4)
                        src = W1T + (size_t)p * W1S + (size_t)(qe * H_ + qh * 128 + nn) * D_ + qc * 64 + c8 * 8;
                    else
                        src = W2T + (size_t)p * W2S + (size_t)(qe * O_ + nn) * H_ + qh * 128 + (qc - 4) * 64 + c8 * 8;
                    CPA(dbase + p * WPL + nn * 144 + c8 * 16, src);
                }
                CPCOMMIT();
            }
        }
    }

    // final epilogue: Out = D2 + sum_e g_e * be2[e]
    #pragma unroll
    for (int i = 0; i < 2; i++) {
        int r0 = mw + i * 16 + (lane >> 2);
        float ga[8], gb[8];
        #pragma unroll
        for (int e = 0; e < 8; e++) { ga[e] = LG[r0 * 8 + e]; gb[e] = LG[(r0 + 8) * 8 + e]; }
        #pragma unroll
        for (int j = 0; j < 2; j++) {
            int col = nw + j * 8 + (lane & 3) * 2;
            float b0a = 0.f, b1a = 0.f, b0b = 0.f, b1b = 0.f;
            #pragma unroll
            for (int e = 0; e < 8; e++) {
                float w0 = be2[e * O_ + col], w1 = be2[e * O_ + col + 1];
                b0a += ga[e] * w0; b1a += ga[e] * w1;
                b0b += gb[e] * w0; b1b += gb[e] * w1;
            }
            *(float2*)(Out + (size_t)(n0 + r0) * O_ + col) =
                make_float2(D2[i][j][0] + b0a, D2[i][j][1] + b1a);
            *(float2*)(Out + (size_t)(n0 + r0 + 8) * O_ + col) =
                make_float2(D2[i][j][2] + b0b, D2[i][j][3] + b1b);
        }
    }
}

// ---------------- generic bf16-split MMA GEMM (tails, round-12) ----------------
#define GAPL 9216
#define GWOF 18432
#define GWPL 18432
#define GEMM2_SMEM (GWOF + 2 * GWPL)

template<bool RELU>
__global__ void __launch_bounds__(NT_, 2)
gemm_mma_kernel(const float* __restrict__ A, const __nv_bfloat16* __restrict__ WT,
                const float* __restrict__ bias, float* __restrict__ Cout,
                int K, int M, const float* __restrict__ S)
{
    extern __shared__ char sm[];
    const int tid = threadIdx.x, lane = tid & 31, wid = tid >> 5;
    const int n0 = blockIdx.x * 64, m0 = blockIdx.y * 128;

    if (S) {
        const int b0 = n0 >> 2;
        bool act = false;
        #pragma unroll
        for (int i = 0; i < 16; i++) act |= (S[b0 + i] != 0.0f);
        if (!act) return;
    }

    const uint32_t sb = smem_u32(sm);
    const size_t WS = (size_t)M * K;
    const int mw = (wid >> 2) * 32, nw = (wid & 3) * 32;
    const int PA[3] = {0, 0, 1}, PB[3] = {0, 1, 0};

    float Cacc[2][4][4];
    #pragma unroll
    for (int i = 0; i < 2; i++)
        #pragma unroll
        for (int j = 0; j < 4; j++)
            #pragma unroll
            for (int q = 0; q < 4; q++) Cacc[i][j][q] = 0.f;

    const uint32_t aoff = (mw + (lane & 15)) * 144 + ((lane >> 4) << 3) * 2;
    const uint32_t boff = GWOF + (nw + (lane >> 4) * 8 + (lane & 7)) * 144 + ((lane >> 3) & 1) * 16;

    for (int kc = 0; kc < (K >> 6); kc++) {
        __syncthreads();
        #pragma unroll
        for (int it = 0; it < 2; it++) {
            int idx = tid + it * 256;
            int row = idx >> 3, c8 = idx & 7;
            const float* srcp = A + (size_t)(n0 + row) * K + kc * 64 + c8 * 8;
            float4 v0 = *(const float4*)srcp;
            float4 v1 = *(const float4*)(srcp + 4);
            float xv[8] = {v0.x, v0.y, v0.z, v0.w, v1.x, v1.y, v1.z, v1.w};
            unsigned short hb[8], lb[8];
            #pragma unroll
            for (int j = 0; j < 8; j++) split2(xv[j], hb[j], lb[j]);
            uint4 u;
            u.x = pack2(hb[0], hb[1]); u.y = pack2(hb[2], hb[3]);
            u.z = pack2(hb[4], hb[5]); u.w = pack2(hb[6], hb[7]);
            *(uint4*)(sm + row * 144 + c8 * 16) = u;
            u.x = pack2(lb[0], lb[1]); u.y = pack2(lb[2], lb[3]);
            u.z = pack2(lb[4], lb[5]); u.w = pack2(lb[6], lb[7]);
            *(uint4*)(sm + GAPL + row * 144 + c8 * 16) = u;
        }
        #pragma unroll
        for (int it = 0; it < 8; it++) {
            int idx = tid + it * 256;
            int p = idx >> 10, rem = idx & 1023, nn = rem >> 3, c8 = rem & 7;
            uint4 v = *(const uint4*)(WT + (size_t)p * WS +
                (size_t)(m0 + nn) * K + kc * 64 + c8 * 8);
            *(uint4*)(sm + GWOF + p * GWPL + nn * 144 + c8 * 16) = v;
        }
        __syncthreads();
        #pragma unroll
        for (int ks = 0; ks < 4; ks++) {
            uint32_t Af[2][2][4], Bf[4][2][2];
            #pragma unroll
            for (int i = 0; i < 2; i++)
                #pragma unroll
                for (int p = 0; p < 2; p++)
                    ldsm4(Af[i][p], sb + aoff + p * GAPL + i * 16 * 144 + ks * 32);
            #pragma unroll
            for (int jj = 0; jj < 2; jj++)
                #pragma unroll
                for (int p = 0; p < 2; p++) {
                    uint32_t r[4];
                    ldsm4(r, sb + boff + p * GWPL + jj * 16 * 144 + ks * 32);
                    Bf[jj * 2][p][0] = r[0];     Bf[jj * 2][p][1] = r[1];
                    Bf[jj * 2 + 1][p][0] = r[2]; Bf[jj * 2 + 1][p][1] = r[3];
                }
            #pragma unroll
            for (int pr = 0; pr < 3; pr++)
                #pragma unroll
                for (int i = 0; i < 2; i++)
                    #pragma unroll
                    for (int j = 0; j < 4; j++)
                        mma16816(Cacc[i][j], Af[i][PA[pr]], Bf[j][PB[pr]]);
        }
    }

    #pragma unroll
    for (int i = 0; i < 2; i++) {
        int r0 = mw + i * 16 + (lane >> 2);
        #pragma unroll
        for (int j = 0; j < 4; j++) {
            int col = m0 + nw + j * 8 + (lane & 3) * 2;
            float b0 = bias[col], b1 = bias[col + 1];
            float v0 = Cacc[i][j][0] + b0, v1 = Cacc[i][j][1] + b1;
            float v2 = Cacc[i][j][2] + b0, v3 = Cacc[i][j][3] + b1;
            if (RELU) {
                v0 = fmaxf(v0, 0.f); v1 = fmaxf(v1, 0.f);
                v2 = fmaxf(v2, 0.f); v3 = fmaxf(v3, 0.f);
            }
            *(float2*)(Cout + (size_t)(n0 + r0) * M + col)     = make_float2(v0, v1);
            *(float2*)(Cout + (size_t)(n0 + r0 + 8) * M + col) = make_float2(v2, v3);
        }
    }
}

// ---------------- small tail kernels ----------------
__global__ void __launch_bounds__(NT_)
gate_update_kernel(float* __restrict__ result, const float* __restrict__ out,
                   float* __restrict__ S, const float* __restrict__ Wog,
                   const float* __restrict__ bog, float thresh)
{
    const int lane = threadIdx.x & 31, wid = threadIdx.x >> 5;
    const int b = blockIdx.x * 8 + wid;
    float s = 0.0f;
    if (out) s = S[b];
    const bool da = (out != nullptr) && (s != 0.0f);
    float* row = result + (size_t)b * CO_;
    const float* orow = da ? (out + (size_t)b * CO_) : nullptr;
    float l0 = 0.0f, l1 = 0.0f;
    for (int k = lane * 4; k < CO_; k += 128) {
        float4 r = *(const float4*)&row[k];
        if (da) {
            float4 o = *(const float4*)&orow[k];
            r.x += o.x * s; r.y += o.y * s; r.z += o.z * s; r.w += o.w * s;
            *(float4*)&row[k] = r;
        }
        float4 wA = *(const float4*)&Wog[2 * k];
        float4 wB = *(const float4*)&Wog[2 * k + 4];
        l0 += r.x * wA.x + r.y * wA.z + r.z * wB.x + r.w * wB.z;
        l1 += r.x * wA.y + r.y * wA.w + r.z * wB.y + r.w * wB.w;
    }
    #pragma unroll
    for (int off = 16; off; off >>= 1) {
        l0 += __shfl_xor_sync(0xffffffffu, l0, off);
        l1 += __shfl_xor_sync(0xffffffffu, l1, off);
    }
    if (lane == 0) {
        l0 += bog[0]; l1 += bog[1];
        float m = fmaxf(l0, l1);
        float e0 = expf(l0 - m), e1 = expf(l1 - m);
        float co0 = e0 / (e0 + e1);
        S[b] = (co0 > thresh) ? co0 : 0.0f;
    }
}

__global__ void __launch_bounds__(NT_)
qhead_kernel(const float* __restrict__ hq, const float* __restrict__ Wq2,
             const float* __restrict__ bq2, float* __restrict__ outv)
{
    __shared__ float W2s[HQ_ * AQ_];
    const int tid = threadIdx.x;
    for (int i = tid; i < HQ_ * AQ_; i += NT_) W2s[i] = Wq2[i];
    __syncthreads();
    const int lane = tid & 31, wid = tid >> 5;
    const int b = blockIdx.x * 8 + wid;
    const float* row = hq + (size_t)b * HQ_;
    float acc[AQ_];
    #pragma unroll
    for (int a = 0; a < AQ_; a++) acc[a] = 0.0f;
    for (int k = lane; k < HQ_; k += 32) {
        float v = row[k];
        const float* wr = &W2s[k * AQ_];
        #pragma unroll
        for (int a = 0; a < AQ_; a++) acc[a] += v * wr[a];
    }
    #pragma unroll
    for (int a = 0; a < AQ_; a++)
        #pragma unroll
        for (int off = 16; off; off >>= 1)
            acc[a] += __shfl_xor_sync(0xffffffffu, acc[a], off);
    if (lane == 0) {
        #pragma unroll
        for (int a = 0; a < AQ_; a++) outv[(size_t)b * AQ_ + a] = acc[a] + bq2[a];
    }
}

// ---------------- launch ----------------
extern "C" void kernel_launch(void* const* d_in, const int* in_sizes, int n_in,
                              void* d_out, int out_size)
{
    const float* data = (const float*)d_in[0];
    const float* We1  = (const float*)d_in[1];
    const float* be1  = (const float*)d_in[2];
    const float* We2  = (const float*)d_in[3];
    const float* be2  = (const float*)d_in[4];
    const float* Wg   = (const float*)d_in[5];
    const float* bg   = (const float*)d_in[6];
    const float* Wog  = (const float*)d_in[7];
    const float* bog  = (const float*)d_in[8];
    const float* Wr   = (const float*)d_in[9];
    const float* br   = (const float*)d_in[10];
    const float* Wq1  = (const float*)d_in[11];
    const float* bq1  = (const float*)d_in[12];
    const float* Wq2  = (const float*)d_in[13];
    const float* bq2  = (const float*)d_in[14];
    float* outp = (float*)d_out;

    cudaFuncSetAttribute(moe_mma_kernel, cudaFuncAttributeMaxDynamicSharedMemorySize, MOE_SMEM);
    cudaFuncSetAttribute(gemm_mma_kernel<false>, cudaFuncAttributeMaxDynamicSharedMemorySize, GEMM2_SMEM);
    cudaFuncSetAttribute(gemm_mma_kernel<true>,  cudaFuncAttributeMaxDynamicSharedMemorySize, GEMM2_SMEM);

    float *res_p, *out_p, *x2_p, *hq_p, *s_p;
    __nv_bfloat16 *xs_p, *w1_p, *w2_p, *wr_p, *wq1_p;
    cudaGetSymbolAddress((void**)&res_p, g_result);
    cudaGetSymbolAddress((void**)&out_p, g_out);
    cudaGetSymbolAddress((void**)&x2_p,  g_x2);
    cudaGetSymbolAddress((void**)&hq_p,  g_hq);
    cudaGetSymbolAddress((void**)&s_p,   g_s);
    cudaGetSymbolAddress((void**)&xs_p,  g_xs);
    cudaGetSymbolAddress((void**)&w1_p,  g_w1t);
    cudaGetSymbolAddress((void**)&w2_p,  g_w2t);
    cudaGetSymbolAddress((void**)&wr_p,  g_wrt);
    cudaGetSymbolAddress((void**)&wq1_p, g_wq1t);

    split_w1_kernel<<<E_ * H_ * D_ / 256, 256>>>(We1);
    split_w2_kernel<<<E_ * O_ * H_ / 256, 256>>>(We2);
    split_wr_kernel<<<D_ * O_ / 256, 256>>>(Wr);
    split_wq1_kernel<<<HQ_ * CO_ / 256, 256>>>(Wq1);

    const dim3 moe_grid(N_ / 64);
    const dim3 sx_grid(N_ * D_ / 4 / 256);
    const dim3 rmap_grid(N_ / 64, 2);
    const dim3 hq_grid(B_ / 64, 4);
    const dim3 row_grid(B_ / 8);

    split_x_kernel<<<sx_grid, 256>>>(data, xs_p);
    moe_mma_kernel<<<moe_grid, MT_, MOE_SMEM>>>(data, xs_p, w1_p, w2_p, be1, be2, Wg, bg, res_p, nullptr);
    gate_update_kernel<<<row_grid, NT_>>>(res_p, nullptr, s_p, Wog, bog, 0.3f);

    for (int it = 0; it < 2; it++) {
        gemm_mma_kernel<false><<<rmap_grid, NT_, GEMM2_SMEM>>>(res_p, wr_p, br, x2_p, O_, D_, s_p);
        split_x_kernel<<<sx_grid, 256>>>(x2_p, xs_p);
        moe_mma_kernel<<<moe_grid, MT_, MOE_SMEM>>>(x2_p, xs_p, w1_p, w2_p, be1, be2, Wg, bg, out_p, s_p);
        gate_update_kernel<<<row_grid, NT_>>>(res_p, out_p, s_p, Wog, bog, 0.5f);
    }

    gemm_mma_kernel<true><<<hq_grid, NT_, GEMM2_SMEM>>>(res_p, wq1_p, bq1, hq_p, HQ_, HQ_, nullptr);
    qhead_kernel<<<row_grid, NT_>>>(hq_p, Wq2, bq2, outp);

    (void)in_sizes; (void)n_in; (void)out_size;
}

// round 14
// speedup vs baseline: 1.1268x; 1.1268x over previous
#include <cuda_runtime.h>
#include <cuda_bf16.h>
#include <stdint.h>
#include <math.h>

#define B_   8192
#define C_   4
#define D_   256
#define E_   8
#define H_   256
#define O_   128
#define CO_  512
#define HQ_  512
#define AQ_  18
#define N_   (B_ * C_)
#define NT_  256

__device__ float g_result[B_ * CO_];
__device__ float g_out   [B_ * CO_];
__device__ float g_x2    [N_ * D_];
__device__ float g_hq    [B_ * HQ_];
__device__ float g_s     [B_];
__device__ __nv_bfloat16 g_xs  [2 * N_ * D_];
__device__ __nv_bfloat16 g_w1t [2 * E_ * H_ * D_];
__device__ __nv_bfloat16 g_w2t [2 * E_ * O_ * H_];
__device__ __nv_bfloat16 g_wrt [2 * D_ * O_];
__device__ __nv_bfloat16 g_wq1t[2 * HQ_ * CO_];

__device__ __forceinline__ uint32_t smem_u32(const void* p) {
    uint32_t a;
    asm("{ .reg .u64 t; cvta.to.shared.u64 t, %1; cvt.u32.u64 %0, t; }" : "=r"(a) : "l"(p));
    return a;
}
__device__ __forceinline__ void ldsm4(uint32_t* r, uint32_t a) {
    asm volatile("ldmatrix.sync.aligned.m8n8.x4.shared.b16 {%0,%1,%2,%3}, [%4];"
                 : "=r"(r[0]), "=r"(r[1]), "=r"(r[2]), "=r"(r[3]) : "r"(a));
}
__device__ __forceinline__ void mma16816(float* c, const uint32_t* a, const uint32_t* b) {
    asm volatile("mma.sync.aligned.m16n8k16.row.col.f32.bf16.bf16.f32 "
                 "{%0,%1,%2,%3}, {%4,%5,%6,%7}, {%8,%9}, {%0,%1,%2,%3};"
                 : "+f"(c[0]), "+f"(c[1]), "+f"(c[2]), "+f"(c[3])
                 : "r"(a[0]), "r"(a[1]), "r"(a[2]), "r"(a[3]), "r"(b[0]), "r"(b[1]));
}
#define CPA(d, s)   asm volatile("cp.async.cg.shared.global [%0], [%1], 16;" :: "r"(d), "l"(s))
#define CPCOMMIT()  asm volatile("cp.async.commit_group;")
#define CPWAIT1()   asm volatile("cp.async.wait_group 1;" ::: "memory")
#define CPWAIT0()   asm volatile("cp.async.wait_group 0;" ::: "memory")

__device__ __forceinline__ void split2(float x, unsigned short& h, unsigned short& l) {
    __nv_bfloat16 b0 = __float2bfloat16(x);
    float r = x - __bfloat162float(b0);
    __nv_bfloat16 b1 = __float2bfloat16(r);
    h = __bfloat16_as_ushort(b0); l = __bfloat16_as_ushort(b1);
}
__device__ __forceinline__ uint32_t pack2(unsigned short a, unsigned short b) {
    return (uint32_t)a | ((uint32_t)b << 16);
}

// ---------------- split kernels (2-plane) ----------------
__global__ void split_x_kernel(const float* __restrict__ src, __nv_bfloat16* __restrict__ dst) {
    size_t i4 = (size_t)blockIdx.x * 256 + threadIdx.x;
    float4 v = ((const float4*)src)[i4];
    float xv[4] = {v.x, v.y, v.z, v.w};
    unsigned short hb[4], lb[4];
    #pragma unroll
    for (int j = 0; j < 4; j++) split2(xv[j], hb[j], lb[j]);
    const size_t S = (size_t)N_ * D_ / 4;
    uint2 u;
    u.x = pack2(hb[0], hb[1]); u.y = pack2(hb[2], hb[3]); ((uint2*)dst)[i4] = u;
    u.x = pack2(lb[0], lb[1]); u.y = pack2(lb[2], lb[3]); ((uint2*)dst)[i4 + S] = u;
}
__global__ void split_w1_kernel(const float* __restrict__ We1) {
    int idx = blockIdx.x * 256 + threadIdx.x;
    int e = idx >> 16, h = (idx >> 8) & 255, d = idx & 255;
    unsigned short hb, lb;
    split2(We1[((e * D_) + d) * H_ + h], hb, lb);
    g_w1t[idx] = __ushort_as_bfloat16(hb);
    g_w1t[idx + E_ * H_ * D_] = __ushort_as_bfloat16(lb);
}
__global__ void split_w2_kernel(const float* __restrict__ We2) {
    int idx = blockIdx.x * 256 + threadIdx.x;
    int e = idx >> 15, o = (idx >> 8) & 127, h = idx & 255;
    unsigned short hb, lb;
    split2(We2[((e * H_) + h) * O_ + o], hb, lb);
    g_w2t[idx] = __ushort_as_bfloat16(hb);
    g_w2t[idx + E_ * O_ * H_] = __ushort_as_bfloat16(lb);
}
__global__ void split_wr_kernel(const float* __restrict__ Wr) {
    int idx = blockIdx.x * 256 + threadIdx.x;
    int m = idx >> 7, k = idx & 127;
    unsigned short hb, lb;
    split2(Wr[k * D_ + m], hb, lb);
    g_wrt[idx] = __ushort_as_bfloat16(hb);
    g_wrt[idx + D_ * O_] = __ushort_as_bfloat16(lb);
}
__global__ void split_wq1_kernel(const float* __restrict__ Wq1) {
    int idx = blockIdx.x * 256 + threadIdx.x;
    int m = idx >> 9, k = idx & 511;
    unsigned short hb, lb;
    split2(Wq1[k * HQ_ + m], hb, lb);
    g_wq1t[idx] = __ushort_as_bfloat16(hb);
    g_wq1t[idx + HQ_ * CO_] = __ushort_as_bfloat16(lb);
}

// ---------------- MoE mma.sync kernel (round-12 geometry + frag DB) ------
#define XPL   33792
#define HPL   17408
#define WPL   18432
#define WBUF  36864
#define XS_OFF 0
#define HB_OFF 67584
#define WB_OFF 102400
#define LG_OFF 212992
#define MOE_SMEM 215040
#define NCHUNK 96

__device__ __forceinline__ void loadA(uint32_t (&A)[2][2][4], uint32_t abase,
                                      int pl, int rs, int kk) {
    #pragma unroll
    for (int i = 0; i < 2; i++)
        #pragma unroll
        for (int p = 0; p < 2; p++)
            ldsm4(A[i][p], abase + p * pl + i * 16 * rs + kk * 2);
}
__device__ __forceinline__ void loadB(uint32_t (&Bf)[4][2][2], uint32_t wb, int ks) {
    #pragma unroll
    for (int jj = 0; jj < 2; jj++)
        #pragma unroll
        for (int p = 0; p < 2; p++) {
            uint32_t r[4];
            ldsm4(r, wb + p * WPL + jj * 16 * 144 + ks * 32);
            Bf[jj * 2][p][0] = r[0];     Bf[jj * 2][p][1] = r[1];
            Bf[jj * 2 + 1][p][0] = r[2]; Bf[jj * 2 + 1][p][1] = r[3];
        }
}
// one k=64 chunk: 4 k-steps, fragments double-buffered (ks+1 loads before ks MMAs)
__device__ __forceinline__ void chunk_mma(float (&Cacc)[2][4][4], uint32_t abase,
                                          int pl, int rs, int kbase, uint32_t wb) {
    uint32_t Af[2][2][2][4], Bf[2][4][2][2];
    loadA(Af[0], abase, pl, rs, kbase);
    loadB(Bf[0], wb, 0);
    #pragma unroll
    for (int ks = 0; ks < 4; ks++) {
        const int cur = ks & 1;
        if (ks < 3) {
            loadA(Af[cur ^ 1], abase, pl, rs, kbase + (ks + 1) * 16);
            loadB(Bf[cur ^ 1], wb, ks + 1);
        }
        const int PA[3] = {0, 0, 1}, PB[3] = {0, 1, 0};
        #pragma unroll
        for (int pr = 0; pr < 3; pr++)
            #pragma unroll
            for (int i = 0; i < 2; i++)
                #pragma unroll
                for (int j = 0; j < 4; j++)
                    mma16816(Cacc[i][j], Af[cur][i][PA[pr]], Bf[cur][j][PB[pr]]);
    }
}

__global__ void __launch_bounds__(NT_, 1)
moe_mma_kernel(const float* __restrict__ Xf, const __nv_bfloat16* __restrict__ XS,
               const __nv_bfloat16* __restrict__ W1T, const __nv_bfloat16* __restrict__ W2T,
               const float* __restrict__ be1, const float* __restrict__ be2,
               const float* __restrict__ Wg,  const float* __restrict__ bg,
               float* __restrict__ Out, const float* __restrict__ S)
{
    extern __shared__ char sm[];
    const int tid = threadIdx.x, lane = tid & 31, wid = tid >> 5;
    const int n0 = blockIdx.x * 64;

    if (S) {
        const int b0 = n0 >> 2;
        bool act = false;
        #pragma unroll
        for (int i = 0; i < 16; i++) act |= (S[b0 + i] != 0.0f);
        if (!act) return;
    }

    const uint32_t sb = smem_u32(sm);
    float* LG = (float*)(sm + LG_OFF);
    const size_t XST = (size_t)N_ * D_;
    const size_t W1S = (size_t)E_ * H_ * D_, W2S = (size_t)E_ * O_ * H_;

    #pragma unroll
    for (int q = 0; q < 2; q++) {
        #pragma unroll
        for (int it = 0; it < 8; it++) {
            int idx = tid + it * 256;
            int p = idx >> 10, rem = idx & 1023, nn = rem >> 3, c8 = rem & 7;
            CPA(sb + WB_OFF + q * WBUF + p * WPL + nn * 144 + c8 * 16,
                W1T + (size_t)p * W1S + (size_t)nn * D_ + q * 64 + c8 * 8);
        }
        CPCOMMIT();
    }

    #pragma unroll
    for (int it = 0; it < 16; it++) {
        int idx = tid + it * 256;
        int p = idx >> 11, rem = idx & 2047;
        int row = rem >> 5, c8 = rem & 31;
        uint4 v = *(const uint4*)(XS + (size_t)p * XST + (size_t)(n0 + row) * D_ + c8 * 8);
        *(uint4*)(sm + XS_OFF + p * XPL + row * 528 + c8 * 16) = v;
    }
    {
        int t = tid >> 2, e0 = (tid & 3) * 2;
        float a0 = 0.f, a1 = 0.f;
        const float* xr = Xf + (size_t)(n0 + t) * D_;
        for (int k = 0; k < D_; k += 4) {
            float4 xv = *(const float4*)(xr + k);
            a0 += xv.x * Wg[(k + 0) * 8 + e0] + xv.y * Wg[(k + 1) * 8 + e0]
                + xv.z * Wg[(k + 2) * 8 + e0] + xv.w * Wg[(k + 3) * 8 + e0];
            a1 += xv.x * Wg[(k + 0) * 8 + e0 + 1] + xv.y * Wg[(k + 1) * 8 + e0 + 1]
                + xv.z * Wg[(k + 2) * 8 + e0 + 1] + xv.w * Wg[(k + 3) * 8 + e0 + 1];
        }
        LG[t * 8 + e0] = a0 + bg[e0];
        LG[t * 8 + e0 + 1] = a1 + bg[e0 + 1];
    }
    __syncthreads();
    if (tid < 64) {
        float m = -1e30f;
        #pragma unroll
        for (int e = 0; e < 8; e++) m = fmaxf(m, LG[tid * 8 + e]);
        float ex[8], ss = 0.f;
        #pragma unroll
        for (int e = 0; e < 8; e++) { ex[e] = expf(LG[tid * 8 + e] - m); ss += ex[e]; }
        float inv = 1.0f / ss;
        #pragma unroll
        for (int e = 0; e < 8; e++) LG[tid * 8 + e] = ex[e] * inv;
    }

    const int mw = (wid >> 2) * 32, nw = (wid & 3) * 32;

    float D2[2][4][4];
    #pragma unroll
    for (int i = 0; i < 2; i++)
        #pragma unroll
        for (int j = 0; j < 4; j++)
            #pragma unroll
            for (int q = 0; q < 4; q++) D2[i][j][q] = 0.f;

    const uint32_t aoffX  = XS_OFF + (mw + (lane & 15)) * 528 + ((lane >> 4) << 3) * 2;
    const uint32_t aoffH  = HB_OFF + (mw + (lane & 15)) * 272 + ((lane >> 4) << 3) * 2;
    const uint32_t boffW4 = WB_OFF + (nw + (lane >> 4) * 8 + (lane & 7)) * 144 + ((lane >> 3) & 1) * 16;

    int gchunk = 0;
    for (int e8 = 0; e8 < 16; e8++) {
        const int e = e8 >> 1, half = e8 & 1;
        float C1[2][4][4];
        #pragma unroll
        for (int i = 0; i < 2; i++)
            #pragma unroll
            for (int j = 0; j < 4; j++)
                #pragma unroll
                for (int q = 0; q < 4; q++) C1[i][j][q] = 0.f;

        for (int c = 0; c < 6; c++, gchunk++) {
            if (gchunk == NCHUNK - 1) { CPWAIT0(); } else { CPWAIT1(); }
            __syncthreads();

            const uint32_t wb = sb + boffW4 + (gchunk % 3) * WBUF;
            if (c < 4) {
                chunk_mma(C1, sb + aoffX, XPL, 528, c * 64, wb);
                if (c == 3) {
                    #pragma unroll
                    for (int i = 0; i < 2; i++) {
                        int r0 = mw + i * 16 + (lane >> 2);
                        float ga = LG[r0 * 8 + e], gb = LG[(r0 + 8) * 8 + e];
                        #pragma unroll
                        for (int j = 0; j < 4; j++) {
                            int col = nw + j * 8 + (lane & 3) * 2;
                            float b1a = be1[e * H_ + half * 128 + col];
                            float b1b = be1[e * H_ + half * 128 + col + 1];
                            float v0 = fmaxf(C1[i][j][0] + b1a, 0.f) * ga;
                            float v1 = fmaxf(C1[i][j][1] + b1b, 0.f) * ga;
                            float v2 = fmaxf(C1[i][j][2] + b1a, 0.f) * gb;
                            float v3 = fmaxf(C1[i][j][3] + b1b, 0.f) * gb;
                            unsigned short h0, l0, h1, l1;
                            uint32_t base0 = HB_OFF + r0 * 272 + col * 2;
                            uint32_t base1 = HB_OFF + (r0 + 8) * 272 + col * 2;
                            split2(v0, h0, l0); split2(v1, h1, l1);
                            *(uint32_t*)(sm + base0)       = pack2(h0, h1);
                            *(uint32_t*)(sm + base0 + HPL) = pack2(l0, l1);
                            split2(v2, h0, l0); split2(v3, h1, l1);
                            *(uint32_t*)(sm + base1)       = pack2(h0, h1);
                            *(uint32_t*)(sm + base1 + HPL) = pack2(l0, l1);
                        }
                    }
                }
            } else {
                chunk_mma(D2, sb + aoffH, HPL, 272, (c - 4) * 64, wb);
            }

            const int q = gchunk + 2;
            if (q < NCHUNK) {
                const int qe8 = q / 6, qc = q - qe8 * 6;
                const int qe = qe8 >> 1, qh = qe8 & 1;
                const uint32_t dbase = sb + WB_OFF + (q % 3) * WBUF;
                #pragma unroll
                for (int it = 0; it < 8; it++) {
                    int idx = tid + it * 256;
                    int p = idx >> 10, rem = idx & 1023, nn = rem >> 3, c8 = rem & 7;
                    const __nv_bfloat16* src;
                    if (qc < 4)
                        src = W1T + (size_t)p * W1S + (size_t)(qe * H_ + qh * 128 + nn) * D_ + qc * 64 + c8 * 8;
                    else
                        src = W2T + (size_t)p * W2S + (size_t)(qe * O_ + nn) * H_ + qh * 128 + (qc - 4) * 64 + c8 * 8;
                    CPA(dbase + p * WPL + nn * 144 + c8 * 16, src);
                }
                CPCOMMIT();
            }
        }
    }

    #pragma unroll
    for (int i = 0; i < 2; i++) {
        int r0 = mw + i * 16 + (lane >> 2);
        float ga[8], gb[8];
        #pragma unroll
        for (int e = 0; e < 8; e++) { ga[e] = LG[r0 * 8 + e]; gb[e] = LG[(r0 + 8) * 8 + e]; }
        #pragma unroll
        for (int j = 0; j < 4; j++) {
            int col = nw + j * 8 + (lane & 3) * 2;
            float b0a = 0.f, b1a = 0.f, b0b = 0.f, b1b = 0.f;
            #pragma unroll
            for (int e = 0; e < 8; e++) {
                float w0 = be2[e * O_ + col], w1 = be2[e * O_ + col + 1];
                b0a += ga[e] * w0; b1a += ga[e] * w1;
                b0b += gb[e] * w0; b1b += gb[e] * w1;
            }
            *(float2*)(Out + (size_t)(n0 + r0) * O_ + col) =
                make_float2(D2[i][j][0] + b0a, D2[i][j][1] + b1a);
            *(float2*)(Out + (size_t)(n0 + r0 + 8) * O_ + col) =
                make_float2(D2[i][j][2] + b0b, D2[i][j][3] + b1b);
        }
    }
}

// ---------------- generic bf16-split MMA GEMM (tails, round-12) ----------------
#define GAPL 9216
#define GWOF 18432
#define GWPL 18432
#define GEMM2_SMEM (GWOF + 2 * GWPL)

template<bool RELU>
__global__ void __launch_bounds__(NT_, 2)
gemm_mma_kernel(const float* __restrict__ A, const __nv_bfloat16* __restrict__ WT,
                const float* __restrict__ bias, float* __restrict__ Cout,
                int K, int M, const float* __restrict__ S)
{
    extern __shared__ char sm[];
    const int tid = threadIdx.x, lane = tid & 31, wid = tid >> 5;
    const int n0 = blockIdx.x * 64, m0 = blockIdx.y * 128;

    if (S) {
        const int b0 = n0 >> 2;
        bool act = false;
        #pragma unroll
        for (int i = 0; i < 16; i++) act |= (S[b0 + i] != 0.0f);
        if (!act) return;
    }

    const uint32_t sb = smem_u32(sm);
    const size_t WS = (size_t)M * K;
    const int mw = (wid >> 2) * 32, nw = (wid & 3) * 32;
    const int PA[3] = {0, 0, 1}, PB[3] = {0, 1, 0};

    float Cacc[2][4][4];
    #pragma unroll
    for (int i = 0; i < 2; i++)
        #pragma unroll
        for (int j = 0; j < 4; j++)
            #pragma unroll
            for (int q = 0; q < 4; q++) Cacc[i][j][q] = 0.f;

    const uint32_t aoff = (mw + (lane & 15)) * 144 + ((lane >> 4) << 3) * 2;
    const uint32_t boff = GWOF + (nw + (lane >> 4) * 8 + (lane & 7)) * 144 + ((lane >> 3) & 1) * 16;

    for (int kc = 0; kc < (K >> 6); kc++) {
        __syncthreads();
        #pragma unroll
        for (int it = 0; it < 2; it++) {
            int idx = tid + it * 256;
            int row = idx >> 3, c8 = idx & 7;
            const float* srcp = A + (size_t)(n0 + row) * K + kc * 64 + c8 * 8;
            float4 v0 = *(const float4*)srcp;
            float4 v1 = *(const float4*)(srcp + 4);
            float xv[8] = {v0.x, v0.y, v0.z, v0.w, v1.x, v1.y, v1.z, v1.w};
            unsigned short hb[8], lb[8];
            #pragma unroll
            for (int j = 0; j < 8; j++) split2(xv[j], hb[j], lb[j]);
            uint4 u;
            u.x = pack2(hb[0], hb[1]); u.y = pack2(hb[2], hb[3]);
            u.z = pack2(hb[4], hb[5]); u.w = pack2(hb[6], hb[7]);
            *(uint4*)(sm + row * 144 + c8 * 16) = u;
            u.x = pack2(lb[0], lb[1]); u.y = pack2(lb[2], lb[3]);
            u.z = pack2(lb[4], lb[5]); u.w = pack2(lb[6], lb[7]);
            *(uint4*)(sm + GAPL + row * 144 + c8 * 16) = u;
        }
        #pragma unroll
        for (int it = 0; it < 8; it++) {
            int idx = tid + it * 256;
            int p = idx >> 10, rem = idx & 1023, nn = rem >> 3, c8 = rem & 7;
            uint4 v = *(const uint4*)(WT + (size_t)p * WS +
                (size_t)(m0 + nn) * K + kc * 64 + c8 * 8);
            *(uint4*)(sm + GWOF + p * GWPL + nn * 144 + c8 * 16) = v;
        }
        __syncthreads();
        #pragma unroll
        for (int ks = 0; ks < 4; ks++) {
            uint32_t Af[2][2][4], Bf[4][2][2];
            #pragma unroll
            for (int i = 0; i < 2; i++)
                #pragma unroll
                for (int p = 0; p < 2; p++)
                    ldsm4(Af[i][p], sb + aoff + p * GAPL + i * 16 * 144 + ks * 32);
            #pragma unroll
            for (int jj = 0; jj < 2; jj++)
                #pragma unroll
                for (int p = 0; p < 2; p++) {
                    uint32_t r[4];
                    ldsm4(r, sb + boff + p * GWPL + jj * 16 * 144 + ks * 32);
                    Bf[jj * 2][p][0] = r[0];     Bf[jj * 2][p][1] = r[1];
                    Bf[jj * 2 + 1][p][0] = r[2]; Bf[jj * 2 + 1][p][1] = r[3];
                }
            #pragma unroll
            for (int pr = 0; pr < 3; pr++)
                #pragma unroll
                for (int i = 0; i < 2; i++)
                    #pragma unroll
                    for (int j = 0; j < 4; j++)
                        mma16816(Cacc[i][j], Af[i][PA[pr]], Bf[j][PB[pr]]);
        }
    }

    #pragma unroll
    for (int i = 0; i < 2; i++) {
        int r0 = mw + i * 16 + (lane >> 2);
        #pragma unroll
        for (int j = 0; j < 4; j++) {
            int col = m0 + nw + j * 8 + (lane & 3) * 2;
            float b0 = bias[col], b1 = bias[col + 1];
            float v0 = Cacc[i][j][0] + b0, v1 = Cacc[i][j][1] + b1;
            float v2 = Cacc[i][j][2] + b0, v3 = Cacc[i][j][3] + b1;
            if (RELU) {
                v0 = fmaxf(v0, 0.f); v1 = fmaxf(v1, 0.f);
                v2 = fmaxf(v2, 0.f); v3 = fmaxf(v3, 0.f);
            }
            *(float2*)(Cout + (size_t)(n0 + r0) * M + col)     = make_float2(v0, v1);
            *(float2*)(Cout + (size_t)(n0 + r0 + 8) * M + col) = make_float2(v2, v3);
        }
    }
}

// ---------------- small tail kernels ----------------
__global__ void __launch_bounds__(NT_)
gate_update_kernel(float* __restrict__ result, const float* __restrict__ out,
                   float* __restrict__ S, const float* __restrict__ Wog,
                   const float* __restrict__ bog, float thresh)
{
    const int lane = threadIdx.x & 31, wid = threadIdx.x >> 5;
    const int b = blockIdx.x * 8 + wid;
    float s = 0.0f;
    if (out) s = S[b];
    const bool da = (out != nullptr) && (s != 0.0f);
    float* row = result + (size_t)b * CO_;
    const float* orow = da ? (out + (size_t)b * CO_) : nullptr;
    float l0 = 0.0f, l1 = 0.0f;
    for (int k = lane * 4; k < CO_; k += 128) {
        float4 r = *(const float4*)&row[k];
        if (da) {
            float4 o = *(const float4*)&orow[k];
            r.x += o.x * s; r.y += o.y * s; r.z += o.z * s; r.w += o.w * s;
            *(float4*)&row[k] = r;
        }
        float4 wA = *(const float4*)&Wog[2 * k];
        float4 wB = *(const float4*)&Wog[2 * k + 4];
        l0 += r.x * wA.x + r.y * wA.z + r.z * wB.x + r.w * wB.z;
        l1 += r.x * wA.y + r.y * wA.w + r.z * wB.y + r.w * wB.w;
    }
    #pragma unroll
    for (int off = 16; off; off >>= 1) {
        l0 += __shfl_xor_sync(0xffffffffu, l0, off);
        l1 += __shfl_xor_sync(0xffffffffu, l1, off);
    }
    if (lane == 0) {
        l0 += bog[0]; l1 += bog[1];
        float m = fmaxf(l0, l1);
        float e0 = expf(l0 - m), e1 = expf(l1 - m);
        float co0 = e0 / (e0 + e1);
        S[b] = (co0 > thresh) ? co0 : 0.0f;
    }
}

__global__ void __launch_bounds__(NT_)
qhead_kernel(const float* __restrict__ hq, const float* __restrict__ Wq2,
             const float* __restrict__ bq2, float* __restrict__ outv)
{
    __shared__ float W2s[HQ_ * AQ_];
    const int tid = threadIdx.x;
    for (int i = tid; i < HQ_ * AQ_; i += NT_) W2s[i] = Wq2[i];
    __syncthreads();
    const int lane = tid & 31, wid = tid >> 5;
    const int b = blockIdx.x * 8 + wid;
    const float* row = hq + (size_t)b * HQ_;
    float acc[AQ_];
    #pragma unroll
    for (int a = 0; a < AQ_; a++) acc[a] = 0.0f;
    for (int k = lane; k < HQ_; k += 32) {
        float v = row[k];
        const float* wr = &W2s[k * AQ_];
        #pragma unroll
        for (int a = 0; a < AQ_; a++) acc[a] += v * wr[a];
    }
    #pragma unroll
    for (int a = 0; a < AQ_; a++)
        #pragma unroll
        for (int off = 16; off; off >>= 1)
            acc[a] += __shfl_xor_sync(0xffffffffu, acc[a], off);
    if (lane == 0) {
        #pragma unroll
        for (int a = 0; a < AQ_; a++) outv[(size_t)b * AQ_ + a] = acc[a] + bq2[a];
    }
}

// ---------------- launch ----------------
extern "C" void kernel_launch(void* const* d_in, const int* in_sizes, int n_in,
                              void* d_out, int out_size)
{
    const float* data = (const float*)d_in[0];
    const float* We1  = (const float*)d_in[1];
    const float* be1  = (const float*)d_in[2];
    const float* We2  = (const float*)d_in[3];
    const float* be2  = (const float*)d_in[4];
    const float* Wg   = (const float*)d_in[5];
    const float* bg   = (const float*)d_in[6];
    const float* Wog  = (const float*)d_in[7];
    const float* bog  = (const float*)d_in[8];
    const float* Wr   = (const float*)d_in[9];
    const float* br   = (const float*)d_in[10];
    const float* Wq1  = (const float*)d_in[11];
    const float* bq1  = (const float*)d_in[12];
    const float* Wq2  = (const float*)d_in[13];
    const float* bq2  = (const float*)d_in[14];
    float* outp = (float*)d_out;

    cudaFuncSetAttribute(moe_mma_kernel, cudaFuncAttributeMaxDynamicSharedMemorySize, MOE_SMEM);
    cudaFuncSetAttribute(gemm_mma_kernel<false>, cudaFuncAttributeMaxDynamicSharedMemorySize, GEMM2_SMEM);
    cudaFuncSetAttribute(gemm_mma_kernel<true>,  cudaFuncAttributeMaxDynamicSharedMemorySize, GEMM2_SMEM);

    float *res_p, *out_p, *x2_p, *hq_p, *s_p;
    __nv_bfloat16 *xs_p, *w1_p, *w2_p, *wr_p, *wq1_p;
    cudaGetSymbolAddress((void**)&res_p, g_result);
    cudaGetSymbolAddress((void**)&out_p, g_out);
    cudaGetSymbolAddress((void**)&x2_p,  g_x2);
    cudaGetSymbolAddress((void**)&hq_p,  g_hq);
    cudaGetSymbolAddress((void**)&s_p,   g_s);
    cudaGetSymbolAddress((void**)&xs_p,  g_xs);
    cudaGetSymbolAddress((void**)&w1_p,  g_w1t);
    cudaGetSymbolAddress((void**)&w2_p,  g_w2t);
    cudaGetSymbolAddress((void**)&wr_p,  g_wrt);
    cudaGetSymbolAddress((void**)&wq1_p, g_wq1t);

    split_w1_kernel<<<E_ * H_ * D_ / 256, 256>>>(We1);
    split_w2_kernel<<<E_ * O_ * H_ / 256, 256>>>(We2);
    split_wr_kernel<<<D_ * O_ / 256, 256>>>(Wr);
    split_wq1_kernel<<<HQ_ * CO_ / 256, 256>>>(Wq1);

    const dim3 moe_grid(N_ / 64);
    const dim3 sx_grid(N_ * D_ / 4 / 256);
    const dim3 rmap_grid(N_ / 64, 2);
    const dim3 hq_grid(B_ / 64, 4);
    const dim3 row_grid(B_ / 8);

    split_x_kernel<<<sx_grid, 256>>>(data, xs_p);
    moe_mma_kernel<<<moe_grid, NT_, MOE_SMEM>>>(data, xs_p, w1_p, w2_p, be1, be2, Wg, bg, res_p, nullptr);
    gate_update_kernel<<<row_grid, NT_>>>(res_p, nullptr, s_p, Wog, bog, 0.3f);

    for (int it = 0; it < 2; it++) {
        gemm_mma_kernel<false><<<rmap_grid, NT_, GEMM2_SMEM>>>(res_p, wr_p, br, x2_p, O_, D_, s_p);
        split_x_kernel<<<sx_grid, 256>>>(x2_p, xs_p);
        moe_mma_kernel<<<moe_grid, NT_, MOE_SMEM>>>(x2_p, xs_p, w1_p, w2_p, be1, be2, Wg, bg, out_p, s_p);
        gate_update_kernel<<<row_grid, NT_>>>(res_p, out_p, s_p, Wog, bog, 0.5f);
    }

    gemm_mma_kernel<true><<<hq_grid, NT_, GEMM2_SMEM>>>(res_p, wq1_p, bq1, hq_p, HQ_, HQ_, nullptr);
    qhead_kernel<<<row_grid, NT_>>>(hq_p, Wq2, bq2, outp);

    (void)in_sizes; (void)n_in; (void)out_size;
}

// round 15
// speedup vs baseline: 1.1750x; 1.0428x over previous
#include <cuda_runtime.h>
#include <cuda_bf16.h>
#include <stdint.h>
#include <math.h>

#define B_   8192
#define C_   4
#define D_   256
#define E_   8
#define H_   256
#define O_   128
#define CO_  512
#define HQ_  512
#define AQ_  18
#define N_   (B_ * C_)
#define NT_  256

__device__ float g_result[B_ * CO_];
__device__ float g_out2  [2 * B_ * CO_];     // partial outputs (expert groups)
__device__ float g_x2    [N_ * D_];
__device__ float g_hq    [B_ * HQ_];
__device__ float g_s     [B_];
__device__ __nv_bfloat16 g_xs  [2 * N_ * D_];
__device__ __nv_bfloat16 g_w1t [2 * E_ * H_ * D_];
__device__ __nv_bfloat16 g_w2t [2 * E_ * O_ * H_];
__device__ __nv_bfloat16 g_wrt [2 * D_ * O_];
__device__ __nv_bfloat16 g_wq1t[2 * HQ_ * CO_];

__device__ __forceinline__ uint32_t smem_u32(const void* p) {
    uint32_t a;
    asm("{ .reg .u64 t; cvta.to.shared.u64 t, %1; cvt.u32.u64 %0, t; }" : "=r"(a) : "l"(p));
    return a;
}
__device__ __forceinline__ void ldsm4(uint32_t* r, uint32_t a) {
    asm volatile("ldmatrix.sync.aligned.m8n8.x4.shared.b16 {%0,%1,%2,%3}, [%4];"
                 : "=r"(r[0]), "=r"(r[1]), "=r"(r[2]), "=r"(r[3]) : "r"(a));
}
__device__ __forceinline__ void mma16816(float* c, const uint32_t* a, const uint32_t* b) {
    asm volatile("mma.sync.aligned.m16n8k16.row.col.f32.bf16.bf16.f32 "
                 "{%0,%1,%2,%3}, {%4,%5,%6,%7}, {%8,%9}, {%0,%1,%2,%3};"
                 : "+f"(c[0]), "+f"(c[1]), "+f"(c[2]), "+f"(c[3])
                 : "r"(a[0]), "r"(a[1]), "r"(a[2]), "r"(a[3]), "r"(b[0]), "r"(b[1]));
}
#define CPA(d, s)   asm volatile("cp.async.cg.shared.global [%0], [%1], 16;" :: "r"(d), "l"(s))
#define CPCOMMIT()  asm volatile("cp.async.commit_group;")
#define CPWAIT1()   asm volatile("cp.async.wait_group 1;" ::: "memory")
#define CPWAIT0()   asm volatile("cp.async.wait_group 0;" ::: "memory")

__device__ __forceinline__ void split2(float x, unsigned short& h, unsigned short& l) {
    __nv_bfloat16 b0 = __float2bfloat16(x);
    float r = x - __bfloat162float(b0);
    __nv_bfloat16 b1 = __float2bfloat16(r);
    h = __bfloat16_as_ushort(b0); l = __bfloat16_as_ushort(b1);
}
__device__ __forceinline__ uint32_t pack2(unsigned short a, unsigned short b) {
    return (uint32_t)a | ((uint32_t)b << 16);
}

// ---------------- split kernels (2-plane) ----------------
__global__ void split_x_kernel(const float* __restrict__ src, __nv_bfloat16* __restrict__ dst) {
    size_t i4 = (size_t)blockIdx.x * 256 + threadIdx.x;
    float4 v = ((const float4*)src)[i4];
    float xv[4] = {v.x, v.y, v.z, v.w};
    unsigned short hb[4], lb[4];
    #pragma unroll
    for (int j = 0; j < 4; j++) split2(xv[j], hb[j], lb[j]);
    const size_t S = (size_t)N_ * D_ / 4;
    uint2 u;
    u.x = pack2(hb[0], hb[1]); u.y = pack2(hb[2], hb[3]); ((uint2*)dst)[i4] = u;
    u.x = pack2(lb[0], lb[1]); u.y = pack2(lb[2], lb[3]); ((uint2*)dst)[i4 + S] = u;
}
__global__ void split_w1_kernel(const float* __restrict__ We1) {
    int idx = blockIdx.x * 256 + threadIdx.x;
    int e = idx >> 16, h = (idx >> 8) & 255, d = idx & 255;
    unsigned short hb, lb;
    split2(We1[((e * D_) + d) * H_ + h], hb, lb);
    g_w1t[idx] = __ushort_as_bfloat16(hb);
    g_w1t[idx + E_ * H_ * D_] = __ushort_as_bfloat16(lb);
}
__global__ void split_w2_kernel(const float* __restrict__ We2) {
    int idx = blockIdx.x * 256 + threadIdx.x;
    int e = idx >> 15, o = (idx >> 8) & 127, h = idx & 255;
    unsigned short hb, lb;
    split2(We2[((e * H_) + h) * O_ + o], hb, lb);
    g_w2t[idx] = __ushort_as_bfloat16(hb);
    g_w2t[idx + E_ * O_ * H_] = __ushort_as_bfloat16(lb);
}
__global__ void split_wr_kernel(const float* __restrict__ Wr) {
    int idx = blockIdx.x * 256 + threadIdx.x;
    int m = idx >> 7, k = idx & 127;
    unsigned short hb, lb;
    split2(Wr[k * D_ + m], hb, lb);
    g_wrt[idx] = __ushort_as_bfloat16(hb);
    g_wrt[idx + D_ * O_] = __ushort_as_bfloat16(lb);
}
__global__ void split_wq1_kernel(const float* __restrict__ Wq1) {
    int idx = blockIdx.x * 256 + threadIdx.x;
    int m = idx >> 9, k = idx & 511;
    unsigned short hb, lb;
    split2(Wq1[k * HQ_ + m], hb, lb);
    g_wq1t[idx] = __ushort_as_bfloat16(hb);
    g_wq1t[idx + HQ_ * CO_] = __ushort_as_bfloat16(lb);
}

// ---------------- MoE mma.sync kernel (expert-group split, 48 chunks) ----
#define XPL   33792
#define HPL   17408
#define WPL   18432
#define WBUF  36864
#define XS_OFF 0
#define HB_OFF 67584
#define WB_OFF 102400
#define LG_OFF 212992
#define MOE_SMEM 215040
#define NCHUNK 48

__device__ __forceinline__ void loadA(uint32_t (&A)[2][2][4], uint32_t abase,
                                      int pl, int rs, int kk) {
    #pragma unroll
    for (int i = 0; i < 2; i++)
        #pragma unroll
        for (int p = 0; p < 2; p++)
            ldsm4(A[i][p], abase + p * pl + i * 16 * rs + kk * 2);
}
__device__ __forceinline__ void loadB(uint32_t (&Bf)[4][2][2], uint32_t wb, int ks) {
    #pragma unroll
    for (int jj = 0; jj < 2; jj++)
        #pragma unroll
        for (int p = 0; p < 2; p++) {
            uint32_t r[4];
            ldsm4(r, wb + p * WPL + jj * 16 * 144 + ks * 32);
            Bf[jj * 2][p][0] = r[0];     Bf[jj * 2][p][1] = r[1];
            Bf[jj * 2 + 1][p][0] = r[2]; Bf[jj * 2 + 1][p][1] = r[3];
        }
}
__device__ __forceinline__ void chunk_mma(float (&Cacc)[2][4][4], uint32_t abase,
                                          int pl, int rs, int kbase, uint32_t wb) {
    uint32_t Af[2][2][2][4], Bf[2][4][2][2];
    loadA(Af[0], abase, pl, rs, kbase);
    loadB(Bf[0], wb, 0);
    #pragma unroll
    for (int ks = 0; ks < 4; ks++) {
        const int cur = ks & 1;
        if (ks < 3) {
            loadA(Af[cur ^ 1], abase, pl, rs, kbase + (ks + 1) * 16);
            loadB(Bf[cur ^ 1], wb, ks + 1);
        }
        const int PA[3] = {0, 0, 1}, PB[3] = {0, 1, 0};
        #pragma unroll
        for (int pr = 0; pr < 3; pr++)
            #pragma unroll
            for (int i = 0; i < 2; i++)
                #pragma unroll
                for (int j = 0; j < 4; j++)
                    mma16816(Cacc[i][j], Af[cur][i][PA[pr]], Bf[cur][j][PB[pr]]);
    }
}

__global__ void __launch_bounds__(NT_, 1)
moe_mma_kernel(const float* __restrict__ Xf, const __nv_bfloat16* __restrict__ XS,
               const __nv_bfloat16* __restrict__ W1T, const __nv_bfloat16* __restrict__ W2T,
               const float* __restrict__ be1, const float* __restrict__ be2,
               const float* __restrict__ Wg,  const float* __restrict__ bg,
               float* __restrict__ Out, const float* __restrict__ S)
{
    extern __shared__ char sm[];
    const int tid = threadIdx.x, lane = tid & 31, wid = tid >> 5;
    const int n0 = blockIdx.x * 64;
    const int eg = blockIdx.y;                 // expert group: 0 -> e 0..3, 1 -> e 4..7
    const int ebase = eg * 4;

    if (S) {
        const int b0 = n0 >> 2;
        bool act = false;
        #pragma unroll
        for (int i = 0; i < 16; i++) act |= (S[b0 + i] != 0.0f);
        if (!act) return;
    }

    const uint32_t sb = smem_u32(sm);
    float* LG = (float*)(sm + LG_OFF);
    const size_t XST = (size_t)N_ * D_;
    const size_t W1S = (size_t)E_ * H_ * D_, W2S = (size_t)E_ * O_ * H_;
    float* Outg = Out + (size_t)eg * B_ * CO_;

    // prologue: chunks 0,1 (W1 e=ebase, half 0)
    #pragma unroll
    for (int q = 0; q < 2; q++) {
        #pragma unroll
        for (int it = 0; it < 8; it++) {
            int idx = tid + it * 256;
            int p = idx >> 10, rem = idx & 1023, nn = rem >> 3, c8 = rem & 7;
            CPA(sb + WB_OFF + q * WBUF + p * WPL + nn * 144 + c8 * 16,
                W1T + (size_t)p * W1S + (size_t)(ebase * H_ + nn) * D_ + q * 64 + c8 * 8);
        }
        CPCOMMIT();
    }

    #pragma unroll
    for (int it = 0; it < 16; it++) {
        int idx = tid + it * 256;
        int p = idx >> 11, rem = idx & 2047;
        int row = rem >> 5, c8 = rem & 31;
        uint4 v = *(const uint4*)(XS + (size_t)p * XST + (size_t)(n0 + row) * D_ + c8 * 8);
        *(uint4*)(sm + XS_OFF + p * XPL + row * 528 + c8 * 16) = v;
    }
    {
        int t = tid >> 2, e0 = (tid & 3) * 2;
        float a0 = 0.f, a1 = 0.f;
        const float* xr = Xf + (size_t)(n0 + t) * D_;
        for (int k = 0; k < D_; k += 4) {
            float4 xv = *(const float4*)(xr + k);
            a0 += xv.x * Wg[(k + 0) * 8 + e0] + xv.y * Wg[(k + 1) * 8 + e0]
                + xv.z * Wg[(k + 2) * 8 + e0] + xv.w * Wg[(k + 3) * 8 + e0];
            a1 += xv.x * Wg[(k + 0) * 8 + e0 + 1] + xv.y * Wg[(k + 1) * 8 + e0 + 1]
                + xv.z * Wg[(k + 2) * 8 + e0 + 1] + xv.w * Wg[(k + 3) * 8 + e0 + 1];
        }
        LG[t * 8 + e0] = a0 + bg[e0];
        LG[t * 8 + e0 + 1] = a1 + bg[e0 + 1];
    }
    __syncthreads();
    if (tid < 64) {
        float m = -1e30f;
        #pragma unroll
        for (int e = 0; e < 8; e++) m = fmaxf(m, LG[tid * 8 + e]);
        float ex[8], ss = 0.f;
        #pragma unroll
        for (int e = 0; e < 8; e++) { ex[e] = expf(LG[tid * 8 + e] - m); ss += ex[e]; }
        float inv = 1.0f / ss;
        #pragma unroll
        for (int e = 0; e < 8; e++) LG[tid * 8 + e] = ex[e] * inv;
    }

    const int mw = (wid >> 2) * 32, nw = (wid & 3) * 32;

    float D2[2][4][4];
    #pragma unroll
    for (int i = 0; i < 2; i++)
        #pragma unroll
        for (int j = 0; j < 4; j++)
            #pragma unroll
            for (int q = 0; q < 4; q++) D2[i][j][q] = 0.f;

    const uint32_t aoffX  = XS_OFF + (mw + (lane & 15)) * 528 + ((lane >> 4) << 3) * 2;
    const uint32_t aoffH  = HB_OFF + (mw + (lane & 15)) * 272 + ((lane >> 4) << 3) * 2;
    const uint32_t boffW4 = WB_OFF + (nw + (lane >> 4) * 8 + (lane & 7)) * 144 + ((lane >> 3) & 1) * 16;

    int gchunk = 0;
    for (int ee = 0; ee < 8; ee++) {
        const int e8 = eg * 8 + ee;
        const int e = e8 >> 1, half = e8 & 1;
        float C1[2][4][4];
        #pragma unroll
        for (int i = 0; i < 2; i++)
            #pragma unroll
            for (int j = 0; j < 4; j++)
                #pragma unroll
                for (int q = 0; q < 4; q++) C1[i][j][q] = 0.f;

        for (int c = 0; c < 6; c++, gchunk++) {
            if (gchunk == NCHUNK - 1) { CPWAIT0(); } else { CPWAIT1(); }
            __syncthreads();

            const uint32_t wb = sb + boffW4 + (gchunk % 3) * WBUF;
            if (c < 4) {
                chunk_mma(C1, sb + aoffX, XPL, 528, c * 64, wb);
                if (c == 3) {
                    #pragma unroll
                    for (int i = 0; i < 2; i++) {
                        int r0 = mw + i * 16 + (lane >> 2);
                        float ga = LG[r0 * 8 + e], gb = LG[(r0 + 8) * 8 + e];
                        #pragma unroll
                        for (int j = 0; j < 4; j++) {
                            int col = nw + j * 8 + (lane & 3) * 2;
                            float b1a = be1[e * H_ + half * 128 + col];
                            float b1b = be1[e * H_ + half * 128 + col + 1];
                            float v0 = fmaxf(C1[i][j][0] + b1a, 0.f) * ga;
                            float v1 = fmaxf(C1[i][j][1] + b1b, 0.f) * ga;
                            float v2 = fmaxf(C1[i][j][2] + b1a, 0.f) * gb;
                            float v3 = fmaxf(C1[i][j][3] + b1b, 0.f) * gb;
                            unsigned short h0, l0, h1, l1;
                            uint32_t base0 = HB_OFF + r0 * 272 + col * 2;
                            uint32_t base1 = HB_OFF + (r0 + 8) * 272 + col * 2;
                            split2(v0, h0, l0); split2(v1, h1, l1);
                            *(uint32_t*)(sm + base0)       = pack2(h0, h1);
                            *(uint32_t*)(sm + base0 + HPL) = pack2(l0, l1);
                            split2(v2, h0, l0); split2(v3, h1, l1);
                            *(uint32_t*)(sm + base1)       = pack2(h0, h1);
                            *(uint32_t*)(sm + base1 + HPL) = pack2(l0, l1);
                        }
                    }
                }
            } else {
                chunk_mma(D2, sb + aoffH, HPL, 272, (c - 4) * 64, wb);
            }

            const int q = gchunk + 2;
            if (q < NCHUNK) {
                const int qee = q / 6, qc = q - qee * 6;
                const int qe8 = eg * 8 + qee;
                const int qe = qe8 >> 1, qh = qe8 & 1;
                const uint32_t dbase = sb + WB_OFF + (q % 3) * WBUF;
                #pragma unroll
                for (int it = 0; it < 8; it++) {
                    int idx = tid + it * 256;
                    int p = idx >> 10, rem = idx & 1023, nn = rem >> 3, c8 = rem & 7;
                    const __nv_bfloat16* src;
                    if (qc < 4)
                        src = W1T + (size_t)p * W1S + (size_t)(qe * H_ + qh * 128 + nn) * D_ + qc * 64 + c8 * 8;
                    else
                        src = W2T + (size_t)p * W2S + (size_t)(qe * O_ + nn) * H_ + qh * 128 + (qc - 4) * 64 + c8 * 8;
                    CPA(dbase + p * WPL + nn * 144 + c8 * 16, src);
                }
                CPCOMMIT();
            }
        }
    }

    // partial epilogue: Outg = D2 + sum_{e in group} g_e * be2[e]
    #pragma unroll
    for (int i = 0; i < 2; i++) {
        int r0 = mw + i * 16 + (lane >> 2);
        float ga[4], gb[4];
        #pragma unroll
        for (int e = 0; e < 4; e++) {
            ga[e] = LG[r0 * 8 + ebase + e];
            gb[e] = LG[(r0 + 8) * 8 + ebase + e];
        }
        #pragma unroll
        for (int j = 0; j < 4; j++) {
            int col = nw + j * 8 + (lane & 3) * 2;
            float b0a = 0.f, b1a = 0.f, b0b = 0.f, b1b = 0.f;
            #pragma unroll
            for (int e = 0; e < 4; e++) {
                float w0 = be2[(ebase + e) * O_ + col], w1 = be2[(ebase + e) * O_ + col + 1];
                b0a += ga[e] * w0; b1a += ga[e] * w1;
                b0b += gb[e] * w0; b1b += gb[e] * w1;
            }
            *(float2*)(Outg + (size_t)(n0 + r0) * O_ + col) =
                make_float2(D2[i][j][0] + b0a, D2[i][j][1] + b1a);
            *(float2*)(Outg + (size_t)(n0 + r0 + 8) * O_ + col) =
                make_float2(D2[i][j][2] + b0b, D2[i][j][3] + b1b);
        }
    }
}

// ---------------- generic bf16-split MMA GEMM (tails) ----------------
// Optional XSP: also emit split planes of the output (rmap fusion; M must be D_).
#define GAPL 9216
#define GWOF 18432
#define GWPL 18432
#define GEMM2_SMEM (GWOF + 2 * GWPL)

template<bool RELU>
__global__ void __launch_bounds__(NT_, 2)
gemm_mma_kernel(const float* __restrict__ A, const __nv_bfloat16* __restrict__ WT,
                const float* __restrict__ bias, float* __restrict__ Cout,
                int K, int M, const float* __restrict__ S,
                __nv_bfloat16* __restrict__ XSP)
{
    extern __shared__ char sm[];
    const int tid = threadIdx.x, lane = tid & 31, wid = tid >> 5;
    const int n0 = blockIdx.x * 64, m0 = blockIdx.y * 128;

    if (S) {
        const int b0 = n0 >> 2;
        bool act = false;
        #pragma unroll
        for (int i = 0; i < 16; i++) act |= (S[b0 + i] != 0.0f);
        if (!act) return;
    }

    const uint32_t sb = smem_u32(sm);
    const size_t WS = (size_t)M * K;
    const int mw = (wid >> 2) * 32, nw = (wid & 3) * 32;
    const int PA[3] = {0, 0, 1}, PB[3] = {0, 1, 0};

    float Cacc[2][4][4];
    #pragma unroll
    for (int i = 0; i < 2; i++)
        #pragma unroll
        for (int j = 0; j < 4; j++)
            #pragma unroll
            for (int q = 0; q < 4; q++) Cacc[i][j][q] = 0.f;

    const uint32_t aoff = (mw + (lane & 15)) * 144 + ((lane >> 4) << 3) * 2;
    const uint32_t boff = GWOF + (nw + (lane >> 4) * 8 + (lane & 7)) * 144 + ((lane >> 3) & 1) * 16;

    for (int kc = 0; kc < (K >> 6); kc++) {
        __syncthreads();
        #pragma unroll
        for (int it = 0; it < 2; it++) {
            int idx = tid + it * 256;
            int row = idx >> 3, c8 = idx & 7;
            const float* srcp = A + (size_t)(n0 + row) * K + kc * 64 + c8 * 8;
            float4 v0 = *(const float4*)srcp;
            float4 v1 = *(const float4*)(srcp + 4);
            float xv[8] = {v0.x, v0.y, v0.z, v0.w, v1.x, v1.y, v1.z, v1.w};
            unsigned short hb[8], lb[8];
            #pragma unroll
            for (int j = 0; j < 8; j++) split2(xv[j], hb[j], lb[j]);
            uint4 u;
            u.x = pack2(hb[0], hb[1]); u.y = pack2(hb[2], hb[3]);
            u.z = pack2(hb[4], hb[5]); u.w = pack2(hb[6], hb[7]);
            *(uint4*)(sm + row * 144 + c8 * 16) = u;
            u.x = pack2(lb[0], lb[1]); u.y = pack2(lb[2], lb[3]);
            u.z = pack2(lb[4], lb[5]); u.w = pack2(lb[6], lb[7]);
            *(uint4*)(sm + GAPL + row * 144 + c8 * 16) = u;
        }
        #pragma unroll
        for (int it = 0; it < 8; it++) {
            int idx = tid + it * 256;
            int p = idx >> 10, rem = idx & 1023, nn = rem >> 3, c8 = rem & 7;
            uint4 v = *(const uint4*)(WT + (size_t)p * WS +
                (size_t)(m0 + nn) * K + kc * 64 + c8 * 8);
            *(uint4*)(sm + GWOF + p * GWPL + nn * 144 + c8 * 16) = v;
        }
        __syncthreads();
        #pragma unroll
        for (int ks = 0; ks < 4; ks++) {
            uint32_t Af[2][2][4], Bf[4][2][2];
            #pragma unroll
            for (int i = 0; i < 2; i++)
                #pragma unroll
                for (int p = 0; p < 2; p++)
                    ldsm4(Af[i][p], sb + aoff + p * GAPL + i * 16 * 144 + ks * 32);
            #pragma unroll
            for (int jj = 0; jj < 2; jj++)
                #pragma unroll
                for (int p = 0; p < 2; p++) {
                    uint32_t r[4];
                    ldsm4(r, sb + boff + p * GWPL + jj * 16 * 144 + ks * 32);
                    Bf[jj * 2][p][0] = r[0];     Bf[jj * 2][p][1] = r[1];
                    Bf[jj * 2 + 1][p][0] = r[2]; Bf[jj * 2 + 1][p][1] = r[3];
                }
            #pragma unroll
            for (int pr = 0; pr < 3; pr++)
                #pragma unroll
                for (int i = 0; i < 2; i++)
                    #pragma unroll
                    for (int j = 0; j < 4; j++)
                        mma16816(Cacc[i][j], Af[i][PA[pr]], Bf[j][PB[pr]]);
        }
    }

    #pragma unroll
    for (int i = 0; i < 2; i++) {
        int r0 = mw + i * 16 + (lane >> 2);
        #pragma unroll
        for (int j = 0; j < 4; j++) {
            int col = m0 + nw + j * 8 + (lane & 3) * 2;
            float b0 = bias[col], b1 = bias[col + 1];
            float v0 = Cacc[i][j][0] + b0, v1 = Cacc[i][j][1] + b1;
            float v2 = Cacc[i][j][2] + b0, v3 = Cacc[i][j][3] + b1;
            if (RELU) {
                v0 = fmaxf(v0, 0.f); v1 = fmaxf(v1, 0.f);
                v2 = fmaxf(v2, 0.f); v3 = fmaxf(v3, 0.f);
            }
            *(float2*)(Cout + (size_t)(n0 + r0) * M + col)     = make_float2(v0, v1);
            *(float2*)(Cout + (size_t)(n0 + r0 + 8) * M + col) = make_float2(v2, v3);
            if (XSP) {   // emit split planes too (rmap fusion, M == D_)
                const size_t PS = (size_t)N_ * D_;
                unsigned short h0, l0, h1, l1;
                split2(v0, h0, l0); split2(v1, h1, l1);
                *(uint32_t*)(XSP + (size_t)(n0 + r0) * D_ + col)      = pack2(h0, h1);
                *(uint32_t*)(XSP + PS + (size_t)(n0 + r0) * D_ + col) = pack2(l0, l1);
                split2(v2, h0, l0); split2(v3, h1, l1);
                *(uint32_t*)(XSP + (size_t)(n0 + r0 + 8) * D_ + col)      = pack2(h0, h1);
                *(uint32_t*)(XSP + PS + (size_t)(n0 + r0 + 8) * D_ + col) = pack2(l0, l1);
            }
        }
    }
}

// ---------------- small tail kernels ----------------
__global__ void __launch_bounds__(NT_)
gate_update_kernel(float* __restrict__ result, const float* __restrict__ pA,
                   const float* __restrict__ pB, float* __restrict__ S,
                   const float* __restrict__ Wog, const float* __restrict__ bog,
                   float thresh, int first)
{
    const int lane = threadIdx.x & 31, wid = threadIdx.x >> 5;
    const int b = blockIdx.x * 8 + wid;
    float s = 0.0f;
    if (!first) s = S[b];
    const bool da = first || (s != 0.0f);

    float* row = result + (size_t)b * CO_;
    const float* ra = pA + (size_t)b * CO_;
    const float* rb = pB + (size_t)b * CO_;
    float l0 = 0.0f, l1 = 0.0f;
    for (int k = lane * 4; k < CO_; k += 128) {
        float4 r;
        if (first) {
            float4 a = *(const float4*)&ra[k];
            float4 bb = *(const float4*)&rb[k];
            r = make_float4(a.x + bb.x, a.y + bb.y, a.z + bb.z, a.w + bb.w);
            *(float4*)&row[k] = r;
        } else {
            r = *(const float4*)&row[k];
            if (da) {
                float4 a = *(const float4*)&ra[k];
                float4 bb = *(const float4*)&rb[k];
                r.x += (a.x + bb.x) * s; r.y += (a.y + bb.y) * s;
                r.z += (a.z + bb.z) * s; r.w += (a.w + bb.w) * s;
                *(float4*)&row[k] = r;
            }
        }
        float4 wA = *(const float4*)&Wog[2 * k];
        float4 wB = *(const float4*)&Wog[2 * k + 4];
        l0 += r.x * wA.x + r.y * wA.z + r.z * wB.x + r.w * wB.z;
        l1 += r.x * wA.y + r.y * wA.w + r.z * wB.y + r.w * wB.w;
    }
    #pragma unroll
    for (int off = 16; off; off >>= 1) {
        l0 += __shfl_xor_sync(0xffffffffu, l0, off);
        l1 += __shfl_xor_sync(0xffffffffu, l1, off);
    }
    if (lane == 0) {
        l0 += bog[0]; l1 += bog[1];
        float m = fmaxf(l0, l1);
        float e0 = expf(l0 - m), e1 = expf(l1 - m);
        float co0 = e0 / (e0 + e1);
        S[b] = (co0 > thresh) ? co0 : 0.0f;
    }
}

__global__ void __launch_bounds__(NT_)
qhead_kernel(const float* __restrict__ hq, const float* __restrict__ Wq2,
             const float* __restrict__ bq2, float* __restrict__ outv)
{
    __shared__ float W2s[HQ_ * AQ_];
    const int tid = threadIdx.x;
    for (int i = tid; i < HQ_ * AQ_; i += NT_) W2s[i] = Wq2[i];
    __syncthreads();
    const int lane = tid & 31, wid = tid >> 5;
    const int b = blockIdx.x * 8 + wid;
    const float* row = hq + (size_t)b * HQ_;
    float acc[AQ_];
    #pragma unroll
    for (int a = 0; a < AQ_; a++) acc[a] = 0.0f;
    for (int k = lane; k < HQ_; k += 32) {
        float v = row[k];
        const float* wr = &W2s[k * AQ_];
        #pragma unroll
        for (int a = 0; a < AQ_; a++) acc[a] += v * wr[a];
    }
    #pragma unroll
    for (int a = 0; a < AQ_; a++)
        #pragma unroll
        for (int off = 16; off; off >>= 1)
            acc[a] += __shfl_xor_sync(0xffffffffu, acc[a], off);
    if (lane == 0) {
        #pragma unroll
        for (int a = 0; a < AQ_; a++) outv[(size_t)b * AQ_ + a] = acc[a] + bq2[a];
    }
}

// ---------------- launch ----------------
extern "C" void kernel_launch(void* const* d_in, const int* in_sizes, int n_in,
                              void* d_out, int out_size)
{
    const float* data = (const float*)d_in[0];
    const float* We1  = (const float*)d_in[1];
    const float* be1  = (const float*)d_in[2];
    const float* We2  = (const float*)d_in[3];
    const float* be2  = (const float*)d_in[4];
    const float* Wg   = (const float*)d_in[5];
    const float* bg   = (const float*)d_in[6];
    const float* Wog  = (const float*)d_in[7];
    const float* bog  = (const float*)d_in[8];
    const float* Wr   = (const float*)d_in[9];
    const float* br   = (const float*)d_in[10];
    const float* Wq1  = (const float*)d_in[11];
    const float* bq1  = (const float*)d_in[12];
    const float* Wq2  = (const float*)d_in[13];
    const float* bq2  = (const float*)d_in[14];
    float* outp = (float*)d_out;

    cudaFuncSetAttribute(moe_mma_kernel, cudaFuncAttributeMaxDynamicSharedMemorySize, MOE_SMEM);
    cudaFuncSetAttribute(gemm_mma_kernel<false>, cudaFuncAttributeMaxDynamicSharedMemorySize, GEMM2_SMEM);
    cudaFuncSetAttribute(gemm_mma_kernel<true>,  cudaFuncAttributeMaxDynamicSharedMemorySize, GEMM2_SMEM);

    float *res_p, *out2_p, *x2_p, *hq_p, *s_p;
    __nv_bfloat16 *xs_p, *w1_p, *w2_p, *wr_p, *wq1_p;
    cudaGetSymbolAddress((void**)&res_p,  g_result);
    cudaGetSymbolAddress((void**)&out2_p, g_out2);
    cudaGetSymbolAddress((void**)&x2_p,   g_x2);
    cudaGetSymbolAddress((void**)&hq_p,   g_hq);
    cudaGetSymbolAddress((void**)&s_p,    g_s);
    cudaGetSymbolAddress((void**)&xs_p,   g_xs);
    cudaGetSymbolAddress((void**)&w1_p,   g_w1t);
    cudaGetSymbolAddress((void**)&w2_p,   g_w2t);
    cudaGetSymbolAddress((void**)&wr_p,   g_wrt);
    cudaGetSymbolAddress((void**)&wq1_p,  g_wq1t);

    split_w1_kernel<<<E_ * H_ * D_ / 256, 256>>>(We1);
    split_w2_kernel<<<E_ * O_ * H_ / 256, 256>>>(We2);
    split_wr_kernel<<<D_ * O_ / 256, 256>>>(Wr);
    split_wq1_kernel<<<HQ_ * CO_ / 256, 256>>>(Wq1);

    const dim3 moe_grid(N_ / 64, 2);         // 512 x 2 expert-groups = 1024 CTAs
    const dim3 sx_grid(N_ * D_ / 4 / 256);
    const dim3 rmap_grid(N_ / 64, 2);
    const dim3 hq_grid(B_ / 64, 4);
    const dim3 row_grid(B_ / 8);

    float* pB = out2_p + (size_t)B_ * CO_;

    split_x_kernel<<<sx_grid, 256>>>(data, xs_p);
    moe_mma_kernel<<<moe_grid, NT_, MOE_SMEM>>>(data, xs_p, w1_p, w2_p, be1, be2, Wg, bg, out2_p, nullptr);
    gate_update_kernel<<<row_grid, NT_>>>(res_p, out2_p, pB, s_p, Wog, bog, 0.3f, 1);

    for (int it = 0; it < 2; it++) {
        gemm_mma_kernel<false><<<rmap_grid, NT_, GEMM2_SMEM>>>(res_p, wr_p, br, x2_p, O_, D_, s_p, xs_p);
        moe_mma_kernel<<<moe_grid, NT_, MOE_SMEM>>>(x2_p, xs_p, w1_p, w2_p, be1, be2, Wg, bg, out2_p, s_p);
        gate_update_kernel<<<row_grid, NT_>>>(res_p, out2_p, pB, s_p, Wog, bog, 0.5f, 0);
    }

    gemm_mma_kernel<true><<<hq_grid, NT_, GEMM2_SMEM>>>(res_p, wq1_p, bq1, hq_p, HQ_, HQ_, nullptr, nullptr);
    qhead_kernel<<<row_grid, NT_>>>(hq_p, Wq2, bq2, outp);

    (void)in_sizes; (void)n_in; (void)out_size;
}

// round 16
// speedup vs baseline: 1.2138x; 1.0330x over previous
#include <cuda_runtime.h>
#include <cuda_bf16.h>
#include <stdint.h>
#include <math.h>

#define B_   8192
#define C_   4
#define D_   256
#define E_   8
#define H_   256
#define O_   128
#define CO_  512
#define HQ_  512
#define AQ_  18
#define N_   (B_ * C_)
#define NT_  256

__device__ float g_result[B_ * CO_];
__device__ float g_out2  [2 * B_ * CO_];
__device__ float g_x2    [N_ * D_];
__device__ float g_hq    [B_ * HQ_];
__device__ float g_s     [B_];
__device__ int   g_list  [B_ + 16];
__device__ int   g_cnt   [1];
__device__ __nv_bfloat16 g_xs  [2 * N_ * D_];
__device__ __nv_bfloat16 g_w1t [2 * E_ * H_ * D_];
__device__ __nv_bfloat16 g_w2t [2 * E_ * O_ * H_];
__device__ __nv_bfloat16 g_wrt [2 * D_ * O_];
__device__ __nv_bfloat16 g_wq1t[2 * HQ_ * CO_];

__device__ __forceinline__ uint32_t smem_u32(const void* p) {
    uint32_t a;
    asm("{ .reg .u64 t; cvta.to.shared.u64 t, %1; cvt.u32.u64 %0, t; }" : "=r"(a) : "l"(p));
    return a;
}
__device__ __forceinline__ void ldsm4(uint32_t* r, uint32_t a) {
    asm volatile("ldmatrix.sync.aligned.m8n8.x4.shared.b16 {%0,%1,%2,%3}, [%4];"
                 : "=r"(r[0]), "=r"(r[1]), "=r"(r[2]), "=r"(r[3]) : "r"(a));
}
__device__ __forceinline__ void mma16816(float* c, const uint32_t* a, const uint32_t* b) {
    asm volatile("mma.sync.aligned.m16n8k16.row.col.f32.bf16.bf16.f32 "
                 "{%0,%1,%2,%3}, {%4,%5,%6,%7}, {%8,%9}, {%0,%1,%2,%3};"
                 : "+f"(c[0]), "+f"(c[1]), "+f"(c[2]), "+f"(c[3])
                 : "r"(a[0]), "r"(a[1]), "r"(a[2]), "r"(a[3]), "r"(b[0]), "r"(b[1]));
}
#define CPA(d, s)   asm volatile("cp.async.cg.shared.global [%0], [%1], 16;" :: "r"(d), "l"(s))
#define CPCOMMIT()  asm volatile("cp.async.commit_group;")
#define CPWAIT1()   asm volatile("cp.async.wait_group 1;" ::: "memory")
#define CPWAIT0()   asm volatile("cp.async.wait_group 0;" ::: "memory")

__device__ __forceinline__ void split2(float x, unsigned short& h, unsigned short& l) {
    __nv_bfloat16 b0 = __float2bfloat16(x);
    float r = x - __bfloat162float(b0);
    __nv_bfloat16 b1 = __float2bfloat16(r);
    h = __bfloat16_as_ushort(b0); l = __bfloat16_as_ushort(b1);
}
__device__ __forceinline__ uint32_t pack2(unsigned short a, unsigned short b) {
    return (uint32_t)a | ((uint32_t)b << 16);
}

// ---------------- split kernels ----------------
__global__ void split_x_kernel(const float* __restrict__ src, __nv_bfloat16* __restrict__ dst) {
    size_t i4 = (size_t)blockIdx.x * 256 + threadIdx.x;
    float4 v = ((const float4*)src)[i4];
    float xv[4] = {v.x, v.y, v.z, v.w};
    unsigned short hb[4], lb[4];
    #pragma unroll
    for (int j = 0; j < 4; j++) split2(xv[j], hb[j], lb[j]);
    const size_t S = (size_t)N_ * D_ / 4;
    uint2 u;
    u.x = pack2(hb[0], hb[1]); u.y = pack2(hb[2], hb[3]); ((uint2*)dst)[i4] = u;
    u.x = pack2(lb[0], lb[1]); u.y = pack2(lb[2], lb[3]); ((uint2*)dst)[i4 + S] = u;
}
__global__ void split_w1_kernel(const float* __restrict__ We1) {
    int idx = blockIdx.x * 256 + threadIdx.x;
    int e = idx >> 16, h = (idx >> 8) & 255, d = idx & 255;
    unsigned short hb, lb;
    split2(We1[((e * D_) + d) * H_ + h], hb, lb);
    g_w1t[idx] = __ushort_as_bfloat16(hb);
    g_w1t[idx + E_ * H_ * D_] = __ushort_as_bfloat16(lb);
}
__global__ void split_w2_kernel(const float* __restrict__ We2) {
    int idx = blockIdx.x * 256 + threadIdx.x;
    int e = idx >> 15, o = (idx >> 8) & 127, h = idx & 255;
    unsigned short hb, lb;
    split2(We2[((e * H_) + h) * O_ + o], hb, lb);
    g_w2t[idx] = __ushort_as_bfloat16(hb);
    g_w2t[idx + E_ * O_ * H_] = __ushort_as_bfloat16(lb);
}
__global__ void split_wr_kernel(const float* __restrict__ Wr) {
    int idx = blockIdx.x * 256 + threadIdx.x;
    int m = idx >> 7, k = idx & 127;
    unsigned short hb, lb;
    split2(Wr[k * D_ + m], hb, lb);
    g_wrt[idx] = __ushort_as_bfloat16(hb);
    g_wrt[idx + D_ * O_] = __ushort_as_bfloat16(lb);
}
__global__ void split_wq1_kernel(const float* __restrict__ Wq1) {
    int idx = blockIdx.x * 256 + threadIdx.x;
    int m = idx >> 9, k = idx & 511;
    unsigned short hb, lb;
    split2(Wq1[k * HQ_ + m], hb, lb);
    g_wq1t[idx] = __ushort_as_bfloat16(hb);
    g_wq1t[idx + HQ_ * CO_] = __ushort_as_bfloat16(lb);
}

// ---------------- compaction: list of active batches (deterministic) ------
__global__ void compact_kernel(const float* __restrict__ S, int* __restrict__ list,
                               int* __restrict__ cnt)
{
    __shared__ int base;
    __shared__ int wsum[8];
    const int tid = threadIdx.x, lane = tid & 31, w = tid >> 5;
    if (tid == 0) base = 0;
    __syncthreads();
    for (int i0 = 0; i0 < B_; i0 += 256) {
        int i = i0 + tid;
        bool a = (S[i] != 0.0f);
        unsigned m = __ballot_sync(0xffffffffu, a);
        int pre = __popc(m & ((1u << lane) - 1u));
        if (lane == 0) wsum[w] = __popc(m);
        __syncthreads();
        int woff = 0;
        #pragma unroll
        for (int k = 0; k < 8; k++) if (k < w) woff += wsum[k];
        if (a) list[base + woff + pre] = i;
        __syncthreads();
        if (tid == 0) {
            int t = 0;
            #pragma unroll
            for (int k = 0; k < 8; k++) t += wsum[k];
            base += t;
        }
        __syncthreads();
    }
    if (tid == 0) {
        int c = base;
        int cp = (c + 15) & ~15;
        int f = (c > 0) ? list[0] : 0;
        for (int i = c; i < cp; i++) list[i] = f;   // pad: duplicates write identical data
        cnt[0] = cp;
    }
}

// ---------------- MoE mma.sync kernel ----------------
#define XPL   33792
#define HPL   17408
#define WPL   18432
#define WBUF  36864
#define XS_OFF 0
#define HB_OFF 67584
#define WB_OFF 102400
#define LG_OFF 212992
#define MOE_SMEM 215040
#define NCHUNK 48

__device__ __forceinline__ void loadA(uint32_t (&A)[2][2][4], uint32_t abase,
                                      int pl, int rs, int kk) {
    #pragma unroll
    for (int i = 0; i < 2; i++)
        #pragma unroll
        for (int p = 0; p < 2; p++)
            ldsm4(A[i][p], abase + p * pl + i * 16 * rs + kk * 2);
}
__device__ __forceinline__ void loadB(uint32_t (&Bf)[4][2][2], uint32_t wb, int ks) {
    #pragma unroll
    for (int jj = 0; jj < 2; jj++)
        #pragma unroll
        for (int p = 0; p < 2; p++) {
            uint32_t r[4];
            ldsm4(r, wb + p * WPL + jj * 16 * 144 + ks * 32);
            Bf[jj * 2][p][0] = r[0];     Bf[jj * 2][p][1] = r[1];
            Bf[jj * 2 + 1][p][0] = r[2]; Bf[jj * 2 + 1][p][1] = r[3];
        }
}
__device__ __forceinline__ void chunk_mma(float (&Cacc)[2][4][4], uint32_t abase,
                                          int pl, int rs, int kbase, uint32_t wb) {
    uint32_t Af[2][2][2][4], Bf[2][4][2][2];
    loadA(Af[0], abase, pl, rs, kbase);
    loadB(Bf[0], wb, 0);
    #pragma unroll
    for (int ks = 0; ks < 4; ks++) {
        const int cur = ks & 1;
        if (ks < 3) {
            loadA(Af[cur ^ 1], abase, pl, rs, kbase + (ks + 1) * 16);
            loadB(Bf[cur ^ 1], wb, ks + 1);
        }
        const int PA[3] = {0, 0, 1}, PB[3] = {0, 1, 0};
        #pragma unroll
        for (int pr = 0; pr < 3; pr++)
            #pragma unroll
            for (int i = 0; i < 2; i++)
                #pragma unroll
                for (int j = 0; j < 4; j++)
                    mma16816(Cacc[i][j], Af[cur][i][PA[pr]], Bf[cur][j][PB[pr]]);
    }
}

__global__ void __launch_bounds__(NT_, 1)
moe_mma_kernel(const float* __restrict__ Xf, const __nv_bfloat16* __restrict__ XS,
               const __nv_bfloat16* __restrict__ W1T, const __nv_bfloat16* __restrict__ W2T,
               const float* __restrict__ be1, const float* __restrict__ be2,
               const float* __restrict__ Wg,  const float* __restrict__ bg,
               float* __restrict__ Out,
               const int* __restrict__ list, const int* __restrict__ cnt)
{
    extern __shared__ char sm[];
    __shared__ int LIDX[16];
    const int tid = threadIdx.x, lane = tid & 31, wid = tid >> 5;
    const int n0 = blockIdx.x * 64;
    const int eg = blockIdx.y;
    const int ebase = eg * 4;

    if (list) {
        if (blockIdx.x * 16 >= cnt[0]) return;
        if (tid < 16) LIDX[tid] = list[blockIdx.x * 16 + tid];
    }

    const uint32_t sb = smem_u32(sm);
    float* LG = (float*)(sm + LG_OFF);
    const size_t XST = (size_t)N_ * D_;
    const size_t W1S = (size_t)E_ * H_ * D_, W2S = (size_t)E_ * O_ * H_;
    float* Outg = Out + (size_t)eg * B_ * CO_;

    #pragma unroll
    for (int q = 0; q < 2; q++) {
        #pragma unroll
        for (int it = 0; it < 8; it++) {
            int idx = tid + it * 256;
            int p = idx >> 10, rem = idx & 1023, nn = rem >> 3, c8 = rem & 7;
            CPA(sb + WB_OFF + q * WBUF + p * WPL + nn * 144 + c8 * 16,
                W1T + (size_t)p * W1S + (size_t)(ebase * H_ + nn) * D_ + q * 64 + c8 * 8);
        }
        CPCOMMIT();
    }

    // X planes (compacted-linear when list != null — producer wrote them compacted)
    #pragma unroll
    for (int it = 0; it < 16; it++) {
        int idx = tid + it * 256;
        int p = idx >> 11, rem = idx & 2047;
        int row = rem >> 5, c8 = rem & 31;
        uint4 v = *(const uint4*)(XS + (size_t)p * XST + (size_t)(n0 + row) * D_ + c8 * 8);
        *(uint4*)(sm + XS_OFF + p * XPL + row * 528 + c8 * 16) = v;
    }
    {
        int t = tid >> 2, e0 = (tid & 3) * 2;
        float a0 = 0.f, a1 = 0.f;
        const float* xr = Xf + (size_t)(n0 + t) * D_;
        for (int k = 0; k < D_; k += 4) {
            float4 xv = *(const float4*)(xr + k);
            a0 += xv.x * Wg[(k + 0) * 8 + e0] + xv.y * Wg[(k + 1) * 8 + e0]
                + xv.z * Wg[(k + 2) * 8 + e0] + xv.w * Wg[(k + 3) * 8 + e0];
            a1 += xv.x * Wg[(k + 0) * 8 + e0 + 1] + xv.y * Wg[(k + 1) * 8 + e0 + 1]
                + xv.z * Wg[(k + 2) * 8 + e0 + 1] + xv.w * Wg[(k + 3) * 8 + e0 + 1];
        }
        LG[t * 8 + e0] = a0 + bg[e0];
        LG[t * 8 + e0 + 1] = a1 + bg[e0 + 1];
    }
    __syncthreads();
    if (tid < 64) {
        float m = -1e30f;
        #pragma unroll
        for (int e = 0; e < 8; e++) m = fmaxf(m, LG[tid * 8 + e]);
        float ex[8], ss = 0.f;
        #pragma unroll
        for (int e = 0; e < 8; e++) { ex[e] = expf(LG[tid * 8 + e] - m); ss += ex[e]; }
        float inv = 1.0f / ss;
        #pragma unroll
        for (int e = 0; e < 8; e++) LG[tid * 8 + e] = ex[e] * inv;
    }

    const int mw = (wid >> 2) * 32, nw = (wid & 3) * 32;

    float D2[2][4][4];
    #pragma unroll
    for (int i = 0; i < 2; i++)
        #pragma unroll
        for (int j = 0; j < 4; j++)
            #pragma unroll
            for (int q = 0; q < 4; q++) D2[i][j][q] = 0.f;

    const uint32_t aoffX  = XS_OFF + (mw + (lane & 15)) * 528 + ((lane >> 4) << 3) * 2;
    const uint32_t aoffH  = HB_OFF + (mw + (lane & 15)) * 272 + ((lane >> 4) << 3) * 2;
    const uint32_t boffW4 = WB_OFF + (nw + (lane >> 4) * 8 + (lane & 7)) * 144 + ((lane >> 3) & 1) * 16;

    int gchunk = 0;
    for (int ee = 0; ee < 8; ee++) {
        const int e8 = eg * 8 + ee;
        const int e = e8 >> 1, half = e8 & 1;
        float C1[2][4][4];
        #pragma unroll
        for (int i = 0; i < 2; i++)
            #pragma unroll
            for (int j = 0; j < 4; j++)
                #pragma unroll
                for (int q = 0; q < 4; q++) C1[i][j][q] = 0.f;

        for (int c = 0; c < 6; c++, gchunk++) {
            if (gchunk == NCHUNK - 1) { CPWAIT0(); } else { CPWAIT1(); }
            __syncthreads();

            const uint32_t wb = sb + boffW4 + (gchunk % 3) * WBUF;
            if (c < 4) {
                chunk_mma(C1, sb + aoffX, XPL, 528, c * 64, wb);
                if (c == 3) {
                    #pragma unroll
                    for (int i = 0; i < 2; i++) {
                        int r0 = mw + i * 16 + (lane >> 2);
                        float ga = LG[r0 * 8 + e], gb = LG[(r0 + 8) * 8 + e];
                        #pragma unroll
                        for (int j = 0; j < 4; j++) {
                            int col = nw + j * 8 + (lane & 3) * 2;
                            float b1a = be1[e * H_ + half * 128 + col];
                            float b1b = be1[e * H_ + half * 128 + col + 1];
                            float v0 = fmaxf(C1[i][j][0] + b1a, 0.f) * ga;
                            float v1 = fmaxf(C1[i][j][1] + b1b, 0.f) * ga;
                            float v2 = fmaxf(C1[i][j][2] + b1a, 0.f) * gb;
                            float v3 = fmaxf(C1[i][j][3] + b1b, 0.f) * gb;
                            unsigned short h0, l0, h1, l1;
                            uint32_t base0 = HB_OFF + r0 * 272 + col * 2;
                            uint32_t base1 = HB_OFF + (r0 + 8) * 272 + col * 2;
                            split2(v0, h0, l0); split2(v1, h1, l1);
                            *(uint32_t*)(sm + base0)       = pack2(h0, h1);
                            *(uint32_t*)(sm + base0 + HPL) = pack2(l0, l1);
                            split2(v2, h0, l0); split2(v3, h1, l1);
                            *(uint32_t*)(sm + base1)       = pack2(h0, h1);
                            *(uint32_t*)(sm + base1 + HPL) = pack2(l0, l1);
                        }
                    }
                }
            } else {
                chunk_mma(D2, sb + aoffH, HPL, 272, (c - 4) * 64, wb);
            }

            const int q = gchunk + 2;
            if (q < NCHUNK) {
                const int qee = q / 6, qc = q - qee * 6;
                const int qe8 = eg * 8 + qee;
                const int qe = qe8 >> 1, qh = qe8 & 1;
                const uint32_t dbase = sb + WB_OFF + (q % 3) * WBUF;
                #pragma unroll
                for (int it = 0; it < 8; it++) {
                    int idx = tid + it * 256;
                    int p = idx >> 10, rem = idx & 1023, nn = rem >> 3, c8 = rem & 7;
                    const __nv_bfloat16* src;
                    if (qc < 4)
                        src = W1T + (size_t)p * W1S + (size_t)(qe * H_ + qh * 128 + nn) * D_ + qc * 64 + c8 * 8;
                    else
                        src = W2T + (size_t)p * W2S + (size_t)(qe * O_ + nn) * H_ + qh * 128 + (qc - 4) * 64 + c8 * 8;
                    CPA(dbase + p * WPL + nn * 144 + c8 * 16, src);
                }
                CPCOMMIT();
            }
        }
    }

    // partial epilogue: scatter rows via list (duplicate padding writes identical data)
    #pragma unroll
    for (int i = 0; i < 2; i++) {
        int r0 = mw + i * 16 + (lane >> 2);
        int na = list ? (LIDX[r0 >> 2] * 4 + (r0 & 3)) : (n0 + r0);
        int nb = list ? (LIDX[(r0 + 8) >> 2] * 4 + ((r0 + 8) & 3)) : (n0 + r0 + 8);
        float ga[4], gb[4];
        #pragma unroll
        for (int e = 0; e < 4; e++) {
            ga[e] = LG[r0 * 8 + ebase + e];
            gb[e] = LG[(r0 + 8) * 8 + ebase + e];
        }
        #pragma unroll
        for (int j = 0; j < 4; j++) {
            int col = nw + j * 8 + (lane & 3) * 2;
            float b0a = 0.f, b1a = 0.f, b0b = 0.f, b1b = 0.f;
            #pragma unroll
            for (int e = 0; e < 4; e++) {
                float w0 = be2[(ebase + e) * O_ + col], w1 = be2[(ebase + e) * O_ + col + 1];
                b0a += ga[e] * w0; b1a += ga[e] * w1;
                b0b += gb[e] * w0; b1b += gb[e] * w1;
            }
            *(float2*)(Outg + (size_t)na * O_ + col) =
                make_float2(D2[i][j][0] + b0a, D2[i][j][1] + b1a);
            *(float2*)(Outg + (size_t)nb * O_ + col) =
                make_float2(D2[i][j][2] + b0b, D2[i][j][3] + b1b);
        }
    }
}

// ---------------- generic bf16-split MMA GEMM ----------------
#define GAPL 9216
#define GWOF 18432
#define GWPL 18432
#define GEMM2_SMEM (GWOF + 2 * GWPL)

template<bool RELU>
__global__ void __launch_bounds__(NT_, 2)
gemm_mma_kernel(const float* __restrict__ A, const __nv_bfloat16* __restrict__ WT,
                const float* __restrict__ bias, float* __restrict__ Cout,
                int K, int M, __nv_bfloat16* __restrict__ XSP,
                const int* __restrict__ list, const int* __restrict__ cnt)
{
    extern __shared__ char sm[];
    __shared__ int LIDX[16];
    const int tid = threadIdx.x, lane = tid & 31, wid = tid >> 5;
    const int n0 = blockIdx.x * 64, m0 = blockIdx.y * 128;

    if (list) {
        if (blockIdx.x * 16 >= cnt[0]) return;
        if (tid < 16) LIDX[tid] = list[blockIdx.x * 16 + tid];
    }

    const uint32_t sb = smem_u32(sm);
    const size_t WS = (size_t)M * K;
    const int mw = (wid >> 2) * 32, nw = (wid & 3) * 32;
    const int PA[3] = {0, 0, 1}, PB[3] = {0, 1, 0};

    float Cacc[2][4][4];
    #pragma unroll
    for (int i = 0; i < 2; i++)
        #pragma unroll
        for (int j = 0; j < 4; j++)
            #pragma unroll
            for (int q = 0; q < 4; q++) Cacc[i][j][q] = 0.f;

    const uint32_t aoff = (mw + (lane & 15)) * 144 + ((lane >> 4) << 3) * 2;
    const uint32_t boff = GWOF + (nw + (lane >> 4) * 8 + (lane & 7)) * 144 + ((lane >> 3) & 1) * 16;

    for (int kc = 0; kc < (K >> 6); kc++) {
        __syncthreads();
        #pragma unroll
        for (int it = 0; it < 2; it++) {
            int idx = tid + it * 256;
            int row = idx >> 3, c8 = idx & 7;
            int grow = list ? (LIDX[row >> 2] * 4 + (row & 3)) : (n0 + row);
            const float* srcp = A + (size_t)grow * K + kc * 64 + c8 * 8;
            float4 v0 = *(const float4*)srcp;
            float4 v1 = *(const float4*)(srcp + 4);
            float xv[8] = {v0.x, v0.y, v0.z, v0.w, v1.x, v1.y, v1.z, v1.w};
            unsigned short hb[8], lb[8];
            #pragma unroll
            for (int j = 0; j < 8; j++) split2(xv[j], hb[j], lb[j]);
            uint4 u;
            u.x = pack2(hb[0], hb[1]); u.y = pack2(hb[2], hb[3]);
            u.z = pack2(hb[4], hb[5]); u.w = pack2(hb[6], hb[7]);
            *(uint4*)(sm + row * 144 + c8 * 16) = u;
            u.x = pack2(lb[0], lb[1]); u.y = pack2(lb[2], lb[3]);
            u.z = pack2(lb[4], lb[5]); u.w = pack2(lb[6], lb[7]);
            *(uint4*)(sm + GAPL + row * 144 + c8 * 16) = u;
        }
        #pragma unroll
        for (int it = 0; it < 8; it++) {
            int idx = tid + it * 256;
            int p = idx >> 10, rem = idx & 1023, nn = rem >> 3, c8 = rem & 7;
            uint4 v = *(const uint4*)(WT + (size_t)p * WS +
                (size_t)(m0 + nn) * K + kc * 64 + c8 * 8);
            *(uint4*)(sm + GWOF + p * GWPL + nn * 144 + c8 * 16) = v;
        }
        __syncthreads();
        #pragma unroll
        for (int ks = 0; ks < 4; ks++) {
            uint32_t Af[2][2][4], Bf[4][2][2];
            #pragma unroll
            for (int i = 0; i < 2; i++)
                #pragma unroll
                for (int p = 0; p < 2; p++)
                    ldsm4(Af[i][p], sb + aoff + p * GAPL + i * 16 * 144 + ks * 32);
            #pragma unroll
            for (int jj = 0; jj < 2; jj++)
                #pragma unroll
                for (int p = 0; p < 2; p++) {
                    uint32_t r[4];
                    ldsm4(r, sb + boff + p * GWPL + jj * 16 * 144 + ks * 32);
                    Bf[jj * 2][p][0] = r[0];     Bf[jj * 2][p][1] = r[1];
                    Bf[jj * 2 + 1][p][0] = r[2]; Bf[jj * 2 + 1][p][1] = r[3];
                }
            #pragma unroll
            for (int pr = 0; pr < 3; pr++)
                #pragma unroll
                for (int i = 0; i < 2; i++)
                    #pragma unroll
                    for (int j = 0; j < 4; j++)
                        mma16816(Cacc[i][j], Af[i][PA[pr]], Bf[j][PB[pr]]);
        }
    }

    // outputs written compacted-linear (consumer reads linear)
    #pragma unroll
    for (int i = 0; i < 2; i++) {
        int r0 = mw + i * 16 + (lane >> 2);
        #pragma unroll
        for (int j = 0; j < 4; j++) {
            int col = m0 + nw + j * 8 + (lane & 3) * 2;
            float b0 = bias[col], b1 = bias[col + 1];
            float v0 = Cacc[i][j][0] + b0, v1 = Cacc[i][j][1] + b1;
            float v2 = Cacc[i][j][2] + b0, v3 = Cacc[i][j][3] + b1;
            if (RELU) {
                v0 = fmaxf(v0, 0.f); v1 = fmaxf(v1, 0.f);
                v2 = fmaxf(v2, 0.f); v3 = fmaxf(v3, 0.f);
            }
            *(float2*)(Cout + (size_t)(n0 + r0) * M + col)     = make_float2(v0, v1);
            *(float2*)(Cout + (size_t)(n0 + r0 + 8) * M + col) = make_float2(v2, v3);
            if (XSP) {
                const size_t PS = (size_t)N_ * D_;
                unsigned short h0, l0, h1, l1;
                split2(v0, h0, l0); split2(v1, h1, l1);
                *(uint32_t*)(XSP + (size_t)(n0 + r0) * D_ + col)      = pack2(h0, h1);
                *(uint32_t*)(XSP + PS + (size_t)(n0 + r0) * D_ + col) = pack2(l0, l1);
                split2(v2, h0, l0); split2(v3, h1, l1);
                *(uint32_t*)(XSP + (size_t)(n0 + r0 + 8) * D_ + col)      = pack2(h0, h1);
                *(uint32_t*)(XSP + PS + (size_t)(n0 + r0 + 8) * D_ + col) = pack2(l0, l1);
            }
        }
    }
}

// ---------------- small tail kernels ----------------
__global__ void __launch_bounds__(NT_)
gate_update_kernel(float* __restrict__ result, const float* __restrict__ pA,
                   const float* __restrict__ pB, float* __restrict__ S,
                   const float* __restrict__ Wog, const float* __restrict__ bog,
                   float thresh, int first)
{
    const int lane = threadIdx.x & 31, wid = threadIdx.x >> 5;
    const int b = blockIdx.x * 8 + wid;
    float s = 0.0f;
    if (!first) s = S[b];
    const bool da = first || (s != 0.0f);

    float* row = result + (size_t)b * CO_;
    const float* ra = pA + (size_t)b * CO_;
    const float* rb = pB + (size_t)b * CO_;
    float l0 = 0.0f, l1 = 0.0f;
    for (int k = lane * 4; k < CO_; k += 128) {
        float4 r;
        if (first) {
            float4 a = *(const float4*)&ra[k];
            float4 bb = *(const float4*)&rb[k];
            r = make_float4(a.x + bb.x, a.y + bb.y, a.z + bb.z, a.w + bb.w);
            *(float4*)&row[k] = r;
        } else {
            r = *(const float4*)&row[k];
            if (da) {
                float4 a = *(const float4*)&ra[k];
                float4 bb = *(const float4*)&rb[k];
                r.x += (a.x + bb.x) * s; r.y += (a.y + bb.y) * s;
                r.z += (a.z + bb.z) * s; r.w += (a.w + bb.w) * s;
                *(float4*)&row[k] = r;
            }
        }
        float4 wA = *(const float4*)&Wog[2 * k];
        float4 wB = *(const float4*)&Wog[2 * k + 4];
        l0 += r.x * wA.x + r.y * wA.z + r.z * wB.x + r.w * wB.z;
        l1 += r.x * wA.y + r.y * wA.w + r.z * wB.y + r.w * wB.w;
    }
    #pragma unroll
    for (int off = 16; off; off >>= 1) {
        l0 += __shfl_xor_sync(0xffffffffu, l0, off);
        l1 += __shfl_xor_sync(0xffffffffu, l1, off);
    }
    if (lane == 0) {
        l0 += bog[0]; l1 += bog[1];
        float m = fmaxf(l0, l1);
        float e0 = expf(l0 - m), e1 = expf(l1 - m);
        float co0 = e0 / (e0 + e1);
        S[b] = (co0 > thresh) ? co0 : 0.0f;
    }
}

__global__ void __launch_bounds__(NT_)
qhead_kernel(const float* __restrict__ hq, const float* __restrict__ Wq2,
             const float* __restrict__ bq2, float* __restrict__ outv)
{
    __shared__ float W2s[HQ_ * AQ_];
    const int tid = threadIdx.x;
    for (int i = tid; i < HQ_ * AQ_; i += NT_) W2s[i] = Wq2[i];
    __syncthreads();
    const int lane = tid & 31, wid = tid >> 5;
    const int b = blockIdx.x * 8 + wid;
    const float* row = hq + (size_t)b * HQ_;
    float acc[AQ_];
    #pragma unroll
    for (int a = 0; a < AQ_; a++) acc[a] = 0.0f;
    for (int k = lane; k < HQ_; k += 32) {
        float v = row[k];
        const float* wr = &W2s[k * AQ_];
        #pragma unroll
        for (int a = 0; a < AQ_; a++) acc[a] += v * wr[a];
    }
    #pragma unroll
    for (int a = 0; a < AQ_; a++)
        #pragma unroll
        for (int off = 16; off; off >>= 1)
            acc[a] += __shfl_xor_sync(0xffffffffu, acc[a], off);
    if (lane == 0) {
        #pragma unroll
        for (int a = 0; a < AQ_; a++) outv[(size_t)b * AQ_ + a] = acc[a] + bq2[a];
    }
}

// ---------------- launch ----------------
extern "C" void kernel_launch(void* const* d_in, const int* in_sizes, int n_in,
                              void* d_out, int out_size)
{
    const float* data = (const float*)d_in[0];
    const float* We1  = (const float*)d_in[1];
    const float* be1  = (const float*)d_in[2];
    const float* We2  = (const float*)d_in[3];
    const float* be2  = (const float*)d_in[4];
    const float* Wg   = (const float*)d_in[5];
    const float* bg   = (const float*)d_in[6];
    const float* Wog  = (const float*)d_in[7];
    const float* bog  = (const float*)d_in[8];
    const float* Wr   = (const float*)d_in[9];
    const float* br   = (const float*)d_in[10];
    const float* Wq1  = (const float*)d_in[11];
    const float* bq1  = (const float*)d_in[12];
    const float* Wq2  = (const float*)d_in[13];
    const float* bq2  = (const float*)d_in[14];
    float* outp = (float*)d_out;

    cudaFuncSetAttribute(moe_mma_kernel, cudaFuncAttributeMaxDynamicSharedMemorySize, MOE_SMEM);
    cudaFuncSetAttribute(gemm_mma_kernel<false>, cudaFuncAttributeMaxDynamicSharedMemorySize, GEMM2_SMEM);
    cudaFuncSetAttribute(gemm_mma_kernel<true>,  cudaFuncAttributeMaxDynamicSharedMemorySize, GEMM2_SMEM);

    float *res_p, *out2_p, *x2_p, *hq_p, *s_p;
    int *list_p, *cnt_p;
    __nv_bfloat16 *xs_p, *w1_p, *w2_p, *wr_p, *wq1_p;
    cudaGetSymbolAddress((void**)&res_p,  g_result);
    cudaGetSymbolAddress((void**)&out2_p, g_out2);
    cudaGetSymbolAddress((void**)&x2_p,   g_x2);
    cudaGetSymbolAddress((void**)&hq_p,   g_hq);
    cudaGetSymbolAddress((void**)&s_p,    g_s);
    cudaGetSymbolAddress((void**)&list_p, g_list);
    cudaGetSymbolAddress((void**)&cnt_p,  g_cnt);
    cudaGetSymbolAddress((void**)&xs_p,   g_xs);
    cudaGetSymbolAddress((void**)&w1_p,   g_w1t);
    cudaGetSymbolAddress((void**)&w2_p,   g_w2t);
    cudaGetSymbolAddress((void**)&wr_p,   g_wrt);
    cudaGetSymbolAddress((void**)&wq1_p,  g_wq1t);

    split_w1_kernel<<<E_ * H_ * D_ / 256, 256>>>(We1);
    split_w2_kernel<<<E_ * O_ * H_ / 256, 256>>>(We2);
    split_wr_kernel<<<D_ * O_ / 256, 256>>>(Wr);
    split_wq1_kernel<<<HQ_ * CO_ / 256, 256>>>(Wq1);

    const dim3 moe_grid(N_ / 64, 2);
    const dim3 sx_grid(N_ * D_ / 4 / 256);
    const dim3 rmap_grid(N_ / 64, 2);
    const dim3 hq_grid(B_ / 64, 4);
    const dim3 row_grid(B_ / 8);

    float* pB = out2_p + (size_t)B_ * CO_;

    split_x_kernel<<<sx_grid, 256>>>(data, xs_p);
    moe_mma_kernel<<<moe_grid, NT_, MOE_SMEM>>>(data, xs_p, w1_p, w2_p, be1, be2, Wg, bg,
                                                out2_p, nullptr, nullptr);
    gate_update_kernel<<<row_grid, NT_>>>(res_p, out2_p, pB, s_p, Wog, bog, 0.3f, 1);

    for (int it = 0; it < 2; it++) {
        compact_kernel<<<1, 256>>>(s_p, list_p, cnt_p);
        gemm_mma_kernel<false><<<rmap_grid, NT_, GEMM2_SMEM>>>(res_p, wr_p, br, x2_p,
                                                               O_, D_, xs_p, list_p, cnt_p);
        moe_mma_kernel<<<moe_grid, NT_, MOE_SMEM>>>(x2_p, xs_p, w1_p, w2_p, be1, be2, Wg, bg,
                                                    out2_p, list_p, cnt_p);
        gate_update_kernel<<<row_grid, NT_>>>(res_p, out2_p, pB, s_p, Wog, bog, 0.5f, 0);
    }

    gemm_mma_kernel<true><<<hq_grid, NT_, GEMM2_SMEM>>>(res_p, wq1_p, bq1, hq_p,
                                                        HQ_, HQ_, nullptr, nullptr, nullptr);
    qhead_kernel<<<row_grid, NT_>>>(hq_p, Wq2, bq2, outp);

    (void)in_sizes; (void)n_in; (void)out_size;
}

// round 17
// speedup vs baseline: 1.2148x; 1.0008x over previous
#include <cuda_runtime.h>
#include <cuda_bf16.h>
#include <stdint.h>
#include <math.h>

#define B_   8192
#define C_   4
#define D_   256
#define E_   8
#define H_   256
#define O_   128
#define CO_  512
#define HQ_  512
#define AQ_  18
#define N_   (B_ * C_)
#define NT_  256

__device__ float g_result[B_ * CO_];
__device__ float g_out2  [2 * B_ * CO_];
__device__ float g_x2    [N_ * D_];
__device__ float g_hq    [B_ * HQ_];
__device__ float g_s     [B_];
__device__ int   g_list  [B_ + 16];
__device__ int   g_cnt   [1];
__device__ __nv_bfloat16 g_xs  [2 * N_ * D_];
__device__ __nv_bfloat16 g_w1t [2 * E_ * H_ * D_];
__device__ __nv_bfloat16 g_w2t [2 * E_ * O_ * H_];
__device__ __nv_bfloat16 g_wrt [2 * D_ * O_];
__device__ __nv_bfloat16 g_wq1t[2 * HQ_ * CO_];

__device__ __forceinline__ uint32_t smem_u32(const void* p) {
    uint32_t a;
    asm("{ .reg .u64 t; cvta.to.shared.u64 t, %1; cvt.u32.u64 %0, t; }" : "=r"(a) : "l"(p));
    return a;
}
__device__ __forceinline__ void ldsm4(uint32_t* r, uint32_t a) {
    asm volatile("ldmatrix.sync.aligned.m8n8.x4.shared.b16 {%0,%1,%2,%3}, [%4];"
                 : "=r"(r[0]), "=r"(r[1]), "=r"(r[2]), "=r"(r[3]) : "r"(a));
}
__device__ __forceinline__ void mma16816(float* c, const uint32_t* a, const uint32_t* b) {
    asm volatile("mma.sync.aligned.m16n8k16.row.col.f32.bf16.bf16.f32 "
                 "{%0,%1,%2,%3}, {%4,%5,%6,%7}, {%8,%9}, {%0,%1,%2,%3};"
                 : "+f"(c[0]), "+f"(c[1]), "+f"(c[2]), "+f"(c[3])
                 : "r"(a[0]), "r"(a[1]), "r"(a[2]), "r"(a[3]), "r"(b[0]), "r"(b[1]));
}
#define CPA(d, s)   asm volatile("cp.async.cg.shared.global [%0], [%1], 16;" :: "r"(d), "l"(s))
#define CPCOMMIT()  asm volatile("cp.async.commit_group;")
#define CPWAIT1()   asm volatile("cp.async.wait_group 1;" ::: "memory")
#define CPWAIT0()   asm volatile("cp.async.wait_group 0;" ::: "memory")

__device__ __forceinline__ void split2(float x, unsigned short& h, unsigned short& l) {
    __nv_bfloat16 b0 = __float2bfloat16(x);
    float r = x - __bfloat162float(b0);
    __nv_bfloat16 b1 = __float2bfloat16(r);
    h = __bfloat16_as_ushort(b0); l = __bfloat16_as_ushort(b1);
}
__device__ __forceinline__ uint32_t pack2(unsigned short a, unsigned short b) {
    return (uint32_t)a | ((uint32_t)b << 16);
}

// ---------------- split kernels ----------------
__global__ void split_x_kernel(const float* __restrict__ src, __nv_bfloat16* __restrict__ dst) {
    size_t i4 = (size_t)blockIdx.x * 256 + threadIdx.x;
    float4 v = ((const float4*)src)[i4];
    float xv[4] = {v.x, v.y, v.z, v.w};
    unsigned short hb[4], lb[4];
    #pragma unroll
    for (int j = 0; j < 4; j++) split2(xv[j], hb[j], lb[j]);
    const size_t S = (size_t)N_ * D_ / 4;
    uint2 u;
    u.x = pack2(hb[0], hb[1]); u.y = pack2(hb[2], hb[3]); ((uint2*)dst)[i4] = u;
    u.x = pack2(lb[0], lb[1]); u.y = pack2(lb[2], lb[3]); ((uint2*)dst)[i4 + S] = u;
}
// one kernel splits all 4 weight tensors (transposed 2-plane layouts)
#define W1N (E_ * H_ * D_)
#define W2N (E_ * O_ * H_)
#define WRN (D_ * O_)
#define WQN (HQ_ * CO_)
__global__ void split_w_all_kernel(const float* __restrict__ We1, const float* __restrict__ We2,
                                   const float* __restrict__ Wr,  const float* __restrict__ Wq1)
{
    int idx = blockIdx.x * 256 + threadIdx.x;
    unsigned short hb, lb;
    if (idx < W1N) {
        int e = idx >> 16, h = (idx >> 8) & 255, d = idx & 255;
        split2(We1[((e * D_) + d) * H_ + h], hb, lb);
        g_w1t[idx] = __ushort_as_bfloat16(hb);
        g_w1t[idx + W1N] = __ushort_as_bfloat16(lb);
        return;
    }
    idx -= W1N;
    if (idx < W2N) {
        int e = idx >> 15, o = (idx >> 8) & 127, h = idx & 255;
        split2(We2[((e * H_) + h) * O_ + o], hb, lb);
        g_w2t[idx] = __ushort_as_bfloat16(hb);
        g_w2t[idx + W2N] = __ushort_as_bfloat16(lb);
        return;
    }
    idx -= W2N;
    if (idx < WRN) {
        int m = idx >> 7, k = idx & 127;
        split2(Wr[k * D_ + m], hb, lb);
        g_wrt[idx] = __ushort_as_bfloat16(hb);
        g_wrt[idx + WRN] = __ushort_as_bfloat16(lb);
        return;
    }
    idx -= WRN;
    if (idx < WQN) {
        int m = idx >> 9, k = idx & 511;
        split2(Wq1[k * HQ_ + m], hb, lb);
        g_wq1t[idx] = __ushort_as_bfloat16(hb);
        g_wq1t[idx + WQN] = __ushort_as_bfloat16(lb);
    }
}

// ---------------- compaction ----------------
__global__ void compact_kernel(const float* __restrict__ S, int* __restrict__ list,
                               int* __restrict__ cnt)
{
    __shared__ int base;
    __shared__ int wsum[8];
    const int tid = threadIdx.x, lane = tid & 31, w = tid >> 5;
    if (tid == 0) base = 0;
    __syncthreads();
    for (int i0 = 0; i0 < B_; i0 += 256) {
        int i = i0 + tid;
        bool a = (S[i] != 0.0f);
        unsigned m = __ballot_sync(0xffffffffu, a);
        int pre = __popc(m & ((1u << lane) - 1u));
        if (lane == 0) wsum[w] = __popc(m);
        __syncthreads();
        int woff = 0;
        #pragma unroll
        for (int k = 0; k < 8; k++) if (k < w) woff += wsum[k];
        if (a) list[base + woff + pre] = i;
        __syncthreads();
        if (tid == 0) {
            int t = 0;
            #pragma unroll
            for (int k = 0; k < 8; k++) t += wsum[k];
            base += t;
        }
        __syncthreads();
    }
    if (tid == 0) {
        int c = base;
        int cp = (c + 15) & ~15;
        int f = (c > 0) ? list[0] : 0;
        for (int i = c; i < cp; i++) list[i] = f;
        cnt[0] = cp;
    }
}

// ---------------- MoE mma.sync kernel (round-16 exact) ----------------
#define XPL   33792
#define HPL   17408
#define WPL   18432
#define WBUF  36864
#define XS_OFF 0
#define HB_OFF 67584
#define WB_OFF 102400
#define LG_OFF 212992
#define MOE_SMEM 215040
#define NCHUNK 48

__device__ __forceinline__ void loadA(uint32_t (&A)[2][2][4], uint32_t abase,
                                      int pl, int rs, int kk) {
    #pragma unroll
    for (int i = 0; i < 2; i++)
        #pragma unroll
        for (int p = 0; p < 2; p++)
            ldsm4(A[i][p], abase + p * pl + i * 16 * rs + kk * 2);
}
__device__ __forceinline__ void loadB(uint32_t (&Bf)[4][2][2], uint32_t wb, int ks) {
    #pragma unroll
    for (int jj = 0; jj < 2; jj++)
        #pragma unroll
        for (int p = 0; p < 2; p++) {
            uint32_t r[4];
            ldsm4(r, wb + p * WPL + jj * 16 * 144 + ks * 32);
            Bf[jj * 2][p][0] = r[0];     Bf[jj * 2][p][1] = r[1];
            Bf[jj * 2 + 1][p][0] = r[2]; Bf[jj * 2 + 1][p][1] = r[3];
        }
}
__device__ __forceinline__ void chunk_mma(float (&Cacc)[2][4][4], uint32_t abase,
                                          int pl, int rs, int kbase, uint32_t wb) {
    uint32_t Af[2][2][2][4], Bf[2][4][2][2];
    loadA(Af[0], abase, pl, rs, kbase);
    loadB(Bf[0], wb, 0);
    #pragma unroll
    for (int ks = 0; ks < 4; ks++) {
        const int cur = ks & 1;
        if (ks < 3) {
            loadA(Af[cur ^ 1], abase, pl, rs, kbase + (ks + 1) * 16);
            loadB(Bf[cur ^ 1], wb, ks + 1);
        }
        const int PA[3] = {0, 0, 1}, PB[3] = {0, 1, 0};
        #pragma unroll
        for (int pr = 0; pr < 3; pr++)
            #pragma unroll
            for (int i = 0; i < 2; i++)
                #pragma unroll
                for (int j = 0; j < 4; j++)
                    mma16816(Cacc[i][j], Af[cur][i][PA[pr]], Bf[cur][j][PB[pr]]);
    }
}

__global__ void __launch_bounds__(NT_, 1)
moe_mma_kernel(const float* __restrict__ Xf, const __nv_bfloat16* __restrict__ XS,
               const __nv_bfloat16* __restrict__ W1T, const __nv_bfloat16* __restrict__ W2T,
               const float* __restrict__ be1, const float* __restrict__ be2,
               const float* __restrict__ Wg,  const float* __restrict__ bg,
               float* __restrict__ Out,
               const int* __restrict__ list, const int* __restrict__ cnt)
{
    extern __shared__ char sm[];
    __shared__ int LIDX[16];
    const int tid = threadIdx.x, lane = tid & 31, wid = tid >> 5;
    const int n0 = blockIdx.x * 64;
    const int eg = blockIdx.y;
    const int ebase = eg * 4;

    if (list) {
        if (blockIdx.x * 16 >= cnt[0]) return;
        if (tid < 16) LIDX[tid] = list[blockIdx.x * 16 + tid];
    }

    const uint32_t sb = smem_u32(sm);
    float* LG = (float*)(sm + LG_OFF);
    const size_t XST = (size_t)N_ * D_;
    const size_t W1S = (size_t)E_ * H_ * D_, W2S = (size_t)E_ * O_ * H_;
    float* Outg = Out + (size_t)eg * B_ * CO_;

    #pragma unroll
    for (int q = 0; q < 2; q++) {
        #pragma unroll
        for (int it = 0; it < 8; it++) {
            int idx = tid + it * 256;
            int p = idx >> 10, rem = idx & 1023, nn = rem >> 3, c8 = rem & 7;
            CPA(sb + WB_OFF + q * WBUF + p * WPL + nn * 144 + c8 * 16,
                W1T + (size_t)p * W1S + (size_t)(ebase * H_ + nn) * D_ + q * 64 + c8 * 8);
        }
        CPCOMMIT();
    }

    #pragma unroll
    for (int it = 0; it < 16; it++) {
        int idx = tid + it * 256;
        int p = idx >> 11, rem = idx & 2047;
        int row = rem >> 5, c8 = rem & 31;
        uint4 v = *(const uint4*)(XS + (size_t)p * XST + (size_t)(n0 + row) * D_ + c8 * 8);
        *(uint4*)(sm + XS_OFF + p * XPL + row * 528 + c8 * 16) = v;
    }
    {
        int t = tid >> 2, e0 = (tid & 3) * 2;
        float a0 = 0.f, a1 = 0.f;
        const float* xr = Xf + (size_t)(n0 + t) * D_;
        for (int k = 0; k < D_; k += 4) {
            float4 xv = *(const float4*)(xr + k);
            a0 += xv.x * Wg[(k + 0) * 8 + e0] + xv.y * Wg[(k + 1) * 8 + e0]
                + xv.z * Wg[(k + 2) * 8 + e0] + xv.w * Wg[(k + 3) * 8 + e0];
            a1 += xv.x * Wg[(k + 0) * 8 + e0 + 1] + xv.y * Wg[(k + 1) * 8 + e0 + 1]
                + xv.z * Wg[(k + 2) * 8 + e0 + 1] + xv.w * Wg[(k + 3) * 8 + e0 + 1];
        }
        LG[t * 8 + e0] = a0 + bg[e0];
        LG[t * 8 + e0 + 1] = a1 + bg[e0 + 1];
    }
    __syncthreads();
    if (tid < 64) {
        float m = -1e30f;
        #pragma unroll
        for (int e = 0; e < 8; e++) m = fmaxf(m, LG[tid * 8 + e]);
        float ex[8], ss = 0.f;
        #pragma unroll
        for (int e = 0; e < 8; e++) { ex[e] = expf(LG[tid * 8 + e] - m); ss += ex[e]; }
        float inv = 1.0f / ss;
        #pragma unroll
        for (int e = 0; e < 8; e++) LG[tid * 8 + e] = ex[e] * inv;
    }

    const int mw = (wid >> 2) * 32, nw = (wid & 3) * 32;

    float D2[2][4][4];
    #pragma unroll
    for (int i = 0; i < 2; i++)
        #pragma unroll
        for (int j = 0; j < 4; j++)
            #pragma unroll
            for (int q = 0; q < 4; q++) D2[i][j][q] = 0.f;

    const uint32_t aoffX  = XS_OFF + (mw + (lane & 15)) * 528 + ((lane >> 4) << 3) * 2;
    const uint32_t aoffH  = HB_OFF + (mw + (lane & 15)) * 272 + ((lane >> 4) << 3) * 2;
    const uint32_t boffW4 = WB_OFF + (nw + (lane >> 4) * 8 + (lane & 7)) * 144 + ((lane >> 3) & 1) * 16;

    int gchunk = 0;
    for (int ee = 0; ee < 8; ee++) {
        const int e8 = eg * 8 + ee;
        const int e = e8 >> 1, half = e8 & 1;
        float C1[2][4][4];
        #pragma unroll
        for (int i = 0; i < 2; i++)
            #pragma unroll
            for (int j = 0; j < 4; j++)
                #pragma unroll
                for (int q = 0; q < 4; q++) C1[i][j][q] = 0.f;

        for (int c = 0; c < 6; c++, gchunk++) {
            if (gchunk == NCHUNK - 1) { CPWAIT0(); } else { CPWAIT1(); }
            __syncthreads();

            const uint32_t wb = sb + boffW4 + (gchunk % 3) * WBUF;
            if (c < 4) {
                chunk_mma(C1, sb + aoffX, XPL, 528, c * 64, wb);
                if (c == 3) {
                    #pragma unroll
                    for (int i = 0; i < 2; i++) {
                        int r0 = mw + i * 16 + (lane >> 2);
                        float ga = LG[r0 * 8 + e], gb = LG[(r0 + 8) * 8 + e];
                        #pragma unroll
                        for (int j = 0; j < 4; j++) {
                            int col = nw + j * 8 + (lane & 3) * 2;
                            float b1a = be1[e * H_ + half * 128 + col];
                            float b1b = be1[e * H_ + half * 128 + col + 1];
                            float v0 = fmaxf(C1[i][j][0] + b1a, 0.f) * ga;
                            float v1 = fmaxf(C1[i][j][1] + b1b, 0.f) * ga;
                            float v2 = fmaxf(C1[i][j][2] + b1a, 0.f) * gb;
                            float v3 = fmaxf(C1[i][j][3] + b1b, 0.f) * gb;
                            unsigned short h0, l0, h1, l1;
                            uint32_t base0 = HB_OFF + r0 * 272 + col * 2;
                            uint32_t base1 = HB_OFF + (r0 + 8) * 272 + col * 2;
                            split2(v0, h0, l0); split2(v1, h1, l1);
                            *(uint32_t*)(sm + base0)       = pack2(h0, h1);
                            *(uint32_t*)(sm + base0 + HPL) = pack2(l0, l1);
                            split2(v2, h0, l0); split2(v3, h1, l1);
                            *(uint32_t*)(sm + base1)       = pack2(h0, h1);
                            *(uint32_t*)(sm + base1 + HPL) = pack2(l0, l1);
                        }
                    }
                }
            } else {
                chunk_mma(D2, sb + aoffH, HPL, 272, (c - 4) * 64, wb);
            }

            const int q = gchunk + 2;
            if (q < NCHUNK) {
                const int qee = q / 6, qc = q - qee * 6;
                const int qe8 = eg * 8 + qee;
                const int qe = qe8 >> 1, qh = qe8 & 1;
                const uint32_t dbase = sb + WB_OFF + (q % 3) * WBUF;
                #pragma unroll
                for (int it = 0; it < 8; it++) {
                    int idx = tid + it * 256;
                    int p = idx >> 10, rem = idx & 1023, nn = rem >> 3, c8 = rem & 7;
                    const __nv_bfloat16* src;
                    if (qc < 4)
                        src = W1T + (size_t)p * W1S + (size_t)(qe * H_ + qh * 128 + nn) * D_ + qc * 64 + c8 * 8;
                    else
                        src = W2T + (size_t)p * W2S + (size_t)(qe * O_ + nn) * H_ + qh * 128 + (qc - 4) * 64 + c8 * 8;
                    CPA(dbase + p * WPL + nn * 144 + c8 * 16, src);
                }
                CPCOMMIT();
            }
        }
    }

    #pragma unroll
    for (int i = 0; i < 2; i++) {
        int r0 = mw + i * 16 + (lane >> 2);
        int na = list ? (LIDX[r0 >> 2] * 4 + (r0 & 3)) : (n0 + r0);
        int nb = list ? (LIDX[(r0 + 8) >> 2] * 4 + ((r0 + 8) & 3)) : (n0 + r0 + 8);
        float ga[4], gb[4];
        #pragma unroll
        for (int e = 0; e < 4; e++) {
            ga[e] = LG[r0 * 8 + ebase + e];
            gb[e] = LG[(r0 + 8) * 8 + ebase + e];
        }
        #pragma unroll
        for (int j = 0; j < 4; j++) {
            int col = nw + j * 8 + (lane & 3) * 2;
            float b0a = 0.f, b1a = 0.f, b0b = 0.f, b1b = 0.f;
            #pragma unroll
            for (int e = 0; e < 4; e++) {
                float w0 = be2[(ebase + e) * O_ + col], w1 = be2[(ebase + e) * O_ + col + 1];
                b0a += ga[e] * w0; b1a += ga[e] * w1;
                b0b += gb[e] * w0; b1b += gb[e] * w1;
            }
            *(float2*)(Outg + (size_t)na * O_ + col) =
                make_float2(D2[i][j][0] + b0a, D2[i][j][1] + b1a);
            *(float2*)(Outg + (size_t)nb * O_ + col) =
                make_float2(D2[i][j][2] + b0b, D2[i][j][3] + b1b);
        }
    }
}

// ---------------- generic bf16-split MMA GEMM (cp.async pipelined) --------
#define GAPL 9216
#define GWOF 18432
#define GWPL 18432
#define GWBUF 36864           // 2 planes per buffer
#define GEMM2_SMEM (GWOF + 2 * GWBUF)   // A planes + 2-buffer W ring = 92160

template<bool RELU>
__global__ void __launch_bounds__(NT_, 2)
gemm_mma_kernel(const float* __restrict__ A, const __nv_bfloat16* __restrict__ WT,
                const float* __restrict__ bias, float* __restrict__ Cout,
                int K, int M, __nv_bfloat16* __restrict__ XSP,
                const int* __restrict__ list, const int* __restrict__ cnt)
{
    extern __shared__ char sm[];
    __shared__ int LIDX[16];
    const int tid = threadIdx.x, lane = tid & 31, wid = tid >> 5;
    const int n0 = blockIdx.x * 64, m0 = blockIdx.y * 128;

    if (list) {
        if (blockIdx.x * 16 >= cnt[0]) return;
        if (tid < 16) LIDX[tid] = list[blockIdx.x * 16 + tid];
    }

    const uint32_t sb = smem_u32(sm);
    const size_t WS = (size_t)M * K;
    const int mw = (wid >> 2) * 32, nw = (wid & 3) * 32;
    const int PA[3] = {0, 0, 1}, PB[3] = {0, 1, 0};
    const int nk = K >> 6;

    // prologue: issue W chunk 0 into buf 0
    #pragma unroll
    for (int it = 0; it < 8; it++) {
        int idx = tid + it * 256;
        int p = idx >> 10, rem = idx & 1023, nn = rem >> 3, c8 = rem & 7;
        CPA(sb + GWOF + p * GWPL + nn * 144 + c8 * 16,
            WT + (size_t)p * WS + (size_t)(m0 + nn) * K + c8 * 8);
    }
    CPCOMMIT();

    float Cacc[2][4][4];
    #pragma unroll
    for (int i = 0; i < 2; i++)
        #pragma unroll
        for (int j = 0; j < 4; j++)
            #pragma unroll
            for (int q = 0; q < 4; q++) Cacc[i][j][q] = 0.f;

    const uint32_t aoff = (mw + (lane & 15)) * 144 + ((lane >> 4) << 3) * 2;
    const uint32_t boff = GWOF + (nw + (lane >> 4) * 8 + (lane & 7)) * 144 + ((lane >> 3) & 1) * 16;

    for (int kc = 0; kc < nk; kc++) {
        __syncthreads();      // reads of chunk kc-1 (A and W slot (kc+1)&1) complete
        // stage A chunk kc (fp32 -> split2 planes)
        #pragma unroll
        for (int it = 0; it < 2; it++) {
            int idx = tid + it * 256;
            int row = idx >> 3, c8 = idx & 7;
            int grow = list ? (LIDX[row >> 2] * 4 + (row & 3)) : (n0 + row);
            const float* srcp = A + (size_t)grow * K + kc * 64 + c8 * 8;
            float4 v0 = *(const float4*)srcp;
            float4 v1 = *(const float4*)(srcp + 4);
            float xv[8] = {v0.x, v0.y, v0.z, v0.w, v1.x, v1.y, v1.z, v1.w};
            unsigned short hb[8], lb[8];
            #pragma unroll
            for (int j = 0; j < 8; j++) split2(xv[j], hb[j], lb[j]);
            uint4 u;
            u.x = pack2(hb[0], hb[1]); u.y = pack2(hb[2], hb[3]);
            u.z = pack2(hb[4], hb[5]); u.w = pack2(hb[6], hb[7]);
            *(uint4*)(sm + row * 144 + c8 * 16) = u;
            u.x = pack2(lb[0], lb[1]); u.y = pack2(lb[2], lb[3]);
            u.z = pack2(lb[4], lb[5]); u.w = pack2(lb[6], lb[7]);
            *(uint4*)(sm + GAPL + row * 144 + c8 * 16) = u;
        }
        // prefetch W chunk kc+1 into the other buffer
        if (kc + 1 < nk) {
            const uint32_t dbase = sb + GWOF + ((kc + 1) & 1) * GWBUF;
            #pragma unroll
            for (int it = 0; it < 8; it++) {
                int idx = tid + it * 256;
                int p = idx >> 10, rem = idx & 1023, nn = rem >> 3, c8 = rem & 7;
                CPA(dbase + p * GWPL + nn * 144 + c8 * 16,
                    WT + (size_t)p * WS + (size_t)(m0 + nn) * K + (kc + 1) * 64 + c8 * 8);
            }
            CPCOMMIT(); CPWAIT1();
        } else {
            CPWAIT0();
        }
        __syncthreads();      // chunk kc W + A visible

        const uint32_t wb = sb + boff + (kc & 1) * GWBUF;
        #pragma unroll
        for (int ks = 0; ks < 4; ks++) {
            uint32_t Af[2][2][4], Bf[4][2][2];
            #pragma unroll
            for (int i = 0; i < 2; i++)
                #pragma unroll
                for (int p = 0; p < 2; p++)
                    ldsm4(Af[i][p], sb + aoff + p * GAPL + i * 16 * 144 + ks * 32);
            #pragma unroll
            for (int jj = 0; jj < 2; jj++)
                #pragma unroll
                for (int p = 0; p < 2; p++) {
                    uint32_t r[4];
                    ldsm4(r, wb + p * GWPL + jj * 16 * 144 + ks * 32);
                    Bf[jj * 2][p][0] = r[0];     Bf[jj * 2][p][1] = r[1];
                    Bf[jj * 2 + 1][p][0] = r[2]; Bf[jj * 2 + 1][p][1] = r[3];
                }
            #pragma unroll
            for (int pr = 0; pr < 3; pr++)
                #pragma unroll
                for (int i = 0; i < 2; i++)
                    #pragma unroll
                    for (int j = 0; j < 4; j++)
                        mma16816(Cacc[i][j], Af[i][PA[pr]], Bf[j][PB[pr]]);
        }
    }

    #pragma unroll
    for (int i = 0; i < 2; i++) {
        int r0 = mw + i * 16 + (lane >> 2);
        #pragma unroll
        for (int j = 0; j < 4; j++) {
            int col = m0 + nw + j * 8 + (lane & 3) * 2;
            float b0 = bias[col], b1 = bias[col + 1];
            float v0 = Cacc[i][j][0] + b0, v1 = Cacc[i][j][1] + b1;
            float v2 = Cacc[i][j][2] + b0, v3 = Cacc[i][j][3] + b1;
            if (RELU) {
                v0 = fmaxf(v0, 0.f); v1 = fmaxf(v1, 0.f);
                v2 = fmaxf(v2, 0.f); v3 = fmaxf(v3, 0.f);
            }
            *(float2*)(Cout + (size_t)(n0 + r0) * M + col)     = make_float2(v0, v1);
            *(float2*)(Cout + (size_t)(n0 + r0 + 8) * M + col) = make_float2(v2, v3);
            if (XSP) {
                const size_t PS = (size_t)N_ * D_;
                unsigned short h0, l0, h1, l1;
                split2(v0, h0, l0); split2(v1, h1, l1);
                *(uint32_t*)(XSP + (size_t)(n0 + r0) * D_ + col)      = pack2(h0, h1);
                *(uint32_t*)(XSP + PS + (size_t)(n0 + r0) * D_ + col) = pack2(l0, l1);
                split2(v2, h0, l0); split2(v3, h1, l1);
                *(uint32_t*)(XSP + (size_t)(n0 + r0 + 8) * D_ + col)      = pack2(h0, h1);
                *(uint32_t*)(XSP + PS + (size_t)(n0 + r0 + 8) * D_ + col) = pack2(l0, l1);
            }
        }
    }
}

// ---------------- small tail kernels ----------------
__global__ void __launch_bounds__(NT_)
gate_update_kernel(float* __restrict__ result, const float* __restrict__ pA,
                   const float* __restrict__ pB, float* __restrict__ S,
                   const float* __restrict__ Wog, const float* __restrict__ bog,
                   float thresh, int first)
{
    const int lane = threadIdx.x & 31, wid = threadIdx.x >> 5;
    const int b = blockIdx.x * 8 + wid;
    float s = 0.0f;
    if (!first) s = S[b];
    const bool da = first || (s != 0.0f);

    float* row = result + (size_t)b * CO_;
    const float* ra = pA + (size_t)b * CO_;
    const float* rb = pB + (size_t)b * CO_;
    float l0 = 0.0f, l1 = 0.0f;
    for (int k = lane * 4; k < CO_; k += 128) {
        float4 r;
        if (first) {
            float4 a = *(const float4*)&ra[k];
            float4 bb = *(const float4*)&rb[k];
            r = make_float4(a.x + bb.x, a.y + bb.y, a.z + bb.z, a.w + bb.w);
            *(float4*)&row[k] = r;
        } else {
            r = *(const float4*)&row[k];
            if (da) {
                float4 a = *(const float4*)&ra[k];
                float4 bb = *(const float4*)&rb[k];
                r.x += (a.x + bb.x) * s; r.y += (a.y + bb.y) * s;
                r.z += (a.z + bb.z) * s; r.w += (a.w + bb.w) * s;
                *(float4*)&row[k] = r;
            }
        }
        float4 wA = *(const float4*)&Wog[2 * k];
        float4 wB = *(const float4*)&Wog[2 * k + 4];
        l0 += r.x * wA.x + r.y * wA.z + r.z * wB.x + r.w * wB.z;
        l1 += r.x * wA.y + r.y * wA.w + r.z * wB.y + r.w * wB.w;
    }
    #pragma unroll
    for (int off = 16; off; off >>= 1) {
        l0 += __shfl_xor_sync(0xffffffffu, l0, off);
        l1 += __shfl_xor_sync(0xffffffffu, l1, off);
    }
    if (lane == 0) {
        l0 += bog[0]; l1 += bog[1];
        float m = fmaxf(l0, l1);
        float e0 = expf(l0 - m), e1 = expf(l1 - m);
        float co0 = e0 / (e0 + e1);
        S[b] = (co0 > thresh) ? co0 : 0.0f;
    }
}

__global__ void __launch_bounds__(NT_)
qhead_kernel(const float* __restrict__ hq, const float* __restrict__ Wq2,
             const float* __restrict__ bq2, float* __restrict__ outv)
{
    __shared__ float W2s[HQ_ * AQ_];
    const int tid = threadIdx.x;
    for (int i = tid; i < HQ_ * AQ_; i += NT_) W2s[i] = Wq2[i];
    __syncthreads();
    const int lane = tid & 31, wid = tid >> 5;
    const int b = blockIdx.x * 8 + wid;
    const float* row = hq + (size_t)b * HQ_;
    float acc[AQ_];
    #pragma unroll
    for (int a = 0; a < AQ_; a++) acc[a] = 0.0f;
    for (int k = lane; k < HQ_; k += 32) {
        float v = row[k];
        const float* wr = &W2s[k * AQ_];
        #pragma unroll
        for (int a = 0; a < AQ_; a++) acc[a] += v * wr[a];
    }
    #pragma unroll
    for (int a = 0; a < AQ_; a++)
        #pragma unroll
        for (int off = 16; off; off >>= 1)
            acc[a] += __shfl_xor_sync(0xffffffffu, acc[a], off);
    if (lane == 0) {
        #pragma unroll
        for (int a = 0; a < AQ_; a++) outv[(size_t)b * AQ_ + a] = acc[a] + bq2[a];
    }
}

// ---------------- launch ----------------
extern "C" void kernel_launch(void* const* d_in, const int* in_sizes, int n_in,
                              void* d_out, int out_size)
{
    const float* data = (const float*)d_in[0];
    const float* We1  = (const float*)d_in[1];
    const float* be1  = (const float*)d_in[2];
    const float* We2  = (const float*)d_in[3];
    const float* be2  = (const float*)d_in[4];
    const float* Wg   = (const float*)d_in[5];
    const float* bg   = (const float*)d_in[6];
    const float* Wog  = (const float*)d_in[7];
    const float* bog  = (const float*)d_in[8];
    const float* Wr   = (const float*)d_in[9];
    const float* br   = (const float*)d_in[10];
    const float* Wq1  = (const float*)d_in[11];
    const float* bq1  = (const float*)d_in[12];
    const float* Wq2  = (const float*)d_in[13];
    const float* bq2  = (const float*)d_in[14];
    float* outp = (float*)d_out;

    cudaFuncSetAttribute(moe_mma_kernel, cudaFuncAttributeMaxDynamicSharedMemorySize, MOE_SMEM);
    cudaFuncSetAttribute(gemm_mma_kernel<false>, cudaFuncAttributeMaxDynamicSharedMemorySize, GEMM2_SMEM);
    cudaFuncSetAttribute(gemm_mma_kernel<true>,  cudaFuncAttributeMaxDynamicSharedMemorySize, GEMM2_SMEM);

    float *res_p, *out2_p, *x2_p, *hq_p, *s_p;
    int *list_p, *cnt_p;
    __nv_bfloat16 *xs_p, *w1_p, *w2_p, *wr_p, *wq1_p;
    cudaGetSymbolAddress((void**)&res_p,  g_result);
    cudaGetSymbolAddress((void**)&out2_p, g_out2);
    cudaGetSymbolAddress((void**)&x2_p,   g_x2);
    cudaGetSymbolAddress((void**)&hq_p,   g_hq);
    cudaGetSymbolAddress((void**)&s_p,    g_s);
    cudaGetSymbolAddress((void**)&list_p, g_list);
    cudaGetSymbolAddress((void**)&cnt_p,  g_cnt);
    cudaGetSymbolAddress((void**)&xs_p,   g_xs);
    cudaGetSymbolAddress((void**)&w1_p,   g_w1t);
    cudaGetSymbolAddress((void**)&w2_p,   g_w2t);
    cudaGetSymbolAddress((void**)&wr_p,   g_wrt);
    cudaGetSymbolAddress((void**)&wq1_p,  g_wq1t);

    const int WTOT = W1N + W2N + WRN + WQN;
    split_w_all_kernel<<<(WTOT + 255) / 256, 256>>>(We1, We2, Wr, Wq1);

    const dim3 moe_grid(N_ / 64, 2);
    const dim3 sx_grid(N_ * D_ / 4 / 256);
    const dim3 rmap_grid(N_ / 64, 2);
    const dim3 hq_grid(B_ / 64, 4);
    const dim3 row_grid(B_ / 8);

    float* pB = out2_p + (size_t)B_ * CO_;

    split_x_kernel<<<sx_grid, 256>>>(data, xs_p);
    moe_mma_kernel<<<moe_grid, NT_, MOE_SMEM>>>(data, xs_p, w1_p, w2_p, be1, be2, Wg, bg,
                                                out2_p, nullptr, nullptr);
    gate_update_kernel<<<row_grid, NT_>>>(res_p, out2_p, pB, s_p, Wog, bog, 0.3f, 1);

    for (int it = 0; it < 2; it++) {
        compact_kernel<<<1, 256>>>(s_p, list_p, cnt_p);
        gemm_mma_kernel<false><<<rmap_grid, NT_, GEMM2_SMEM>>>(res_p, wr_p, br, x2_p,
                                                               O_, D_, xs_p, list_p, cnt_p);
        moe_mma_kernel<<<moe_grid, NT_, MOE_SMEM>>>(x2_p, xs_p, w1_p, w2_p, be1, be2, Wg, bg,
                                                    out2_p, list_p, cnt_p);
        gate_update_kernel<<<row_grid, NT_>>>(res_p, out2_p, pB, s_p, Wog, bog, 0.5f, 0);
    }

    gemm_mma_kernel<true><<<hq_grid, NT_, GEMM2_SMEM>>>(res_p, wq1_p, bq1, hq_p,
                                                        HQ_, HQ_, nullptr, nullptr, nullptr);
    qhead_kernel<<<row_grid, NT_>>>(hq_p, Wq2, bq2, outp);

    (void)in_sizes; (void)n_in; (void)out_size;
}